// round 12
// baseline (speedup 1.0000x reference)
#include <cuda_runtime.h>
#include <cuda_bf16.h>
#include <cstdint>

// ===========================================================================
// AttentionGate via mma.sync bf16 split-precision (bf16x3) GEMMs.
// (tcgen05 unavailable: harness PTX targets sm_103, not sm_103a.)
//   x = hi + lo (bf16 each);  x*y ~= hi*hi + hi*lo + lo*hi  (fp32 accum)
// R12: 3-stage cp.async mainloop, ONE __syncthreads per chunk, product-pass
//      MMA ordering for ILP.
// ===========================================================================

#define BATCH 8
#define SEQ   2048
#define DIM   512
#define MTOT  (BATCH * SEQ)          // 16384
#define NTOK  ((size_t)MTOT * DIM)   // 8388608

// ---------------- scratch (__device__ globals; allocation-free) -----------
__device__ __nv_bfloat16 g_qh[NTOK],  g_ql[NTOK];
__device__ __nv_bfloat16 g_kh[NTOK],  g_kl[NTOK];
__device__ __nv_bfloat16 g_vh[NTOK],  g_vl[NTOK];
__device__ __nv_bfloat16 g_wqh[DIM*DIM], g_wql[DIM*DIM];
__device__ __nv_bfloat16 g_wkh[DIM*DIM], g_wkl[DIM*DIM];
__device__ __nv_bfloat16 g_wvh[DIM*DIM], g_wvl[DIM*DIM];
__device__ __nv_bfloat16 g_qph[NTOK], g_qpl[NTOK];
__device__ __nv_bfloat16 g_kph[NTOK], g_kpl[NTOK];
__device__ __nv_bfloat16 g_vth[NTOK], g_vtl[NTOK];
__device__ float         g_sc[(size_t)BATCH * SEQ * SEQ];     // 128 MB
__device__ __nv_bfloat16 g_ph[(size_t)BATCH * SEQ * SEQ];
__device__ __nv_bfloat16 g_pl[(size_t)BATCH * SEQ * SEQ];

// ---------------- PTX helpers (sm_80-era: legal on plain sm_103) ----------
__device__ __forceinline__ uint32_t s2u(const void* p) {
    uint32_t a;
    asm("{ .reg .u64 t; cvta.to.shared.u64 t, %1; cvt.u32.u64 %0, t; }"
        : "=r"(a) : "l"(p));
    return a;
}
__device__ __forceinline__ void cpa16(uint32_t s, const void* g) {
    asm volatile("cp.async.cg.shared.global [%0], [%1], 16;" :: "r"(s), "l"(g));
}
__device__ __forceinline__ void cpa_commit() {
    asm volatile("cp.async.commit_group;" ::: "memory");
}
template <int N>
__device__ __forceinline__ void cpa_wait() {
    asm volatile("cp.async.wait_group %0;" :: "n"(N) : "memory");
}
__device__ __forceinline__ void ldsm4(uint32_t* r, uint32_t a) {
    asm volatile("ldmatrix.sync.aligned.m8n8.x4.shared.b16 {%0,%1,%2,%3}, [%4];"
        : "=r"(r[0]), "=r"(r[1]), "=r"(r[2]), "=r"(r[3]) : "r"(a));
}
__device__ __forceinline__ void mma_bf16(float* d, const uint32_t* a, const uint32_t* b) {
    asm volatile(
        "mma.sync.aligned.m16n8k16.row.col.f32.bf16.bf16.f32 "
        "{%0,%1,%2,%3},{%4,%5,%6,%7},{%8,%9},{%0,%1,%2,%3};"
        : "+f"(d[0]), "+f"(d[1]), "+f"(d[2]), "+f"(d[3])
        : "r"(a[0]), "r"(a[1]), "r"(a[2]), "r"(a[3]), "r"(b[0]), "r"(b[1]));
}
__device__ __forceinline__ void split2(float x, __nv_bfloat16& h, __nv_bfloat16& l) {
    h = __float2bfloat16(x);
    l = __float2bfloat16(x - __bfloat162float(h));
}

// ===========================================================================
// mma.sync bf16x3 GEMM:  C[M,N] = (A * B^T + bias) * scale  (per grid.z batch)
//   CTA tile 128x128, KC=64, 3-stage cp.async (one sync per chunk),
//   8 warps (2m x 4n), 64x32 per warp.
// ===========================================================================
#define BM 128
#define BN 128
#define KC 64
#define STAGE_BYTES 65536            // Ah 16K | Al 16K | Bh 16K | Bl 16K
#define NSTAGE 3
#define GEMM_SMEM   (NSTAGE * STAGE_BYTES)

template <int BIAS_MODE, bool SPLIT_OUT>
__global__ void __launch_bounds__(256, 1)
gemm3(const __nv_bfloat16* __restrict__ Ah, const __nv_bfloat16* __restrict__ Al,
      const __nv_bfloat16* __restrict__ Bh, const __nv_bfloat16* __restrict__ Bl,
      const float* __restrict__ bias,
      float* __restrict__ Cf, __nv_bfloat16* __restrict__ Ch, __nv_bfloat16* __restrict__ Cl,
      int K, int lda, int ldb, int ldc,
      long long sA, long long sB, long long sC, float scale)
{
    extern __shared__ __align__(1024) char smem[];
    const uint32_t sb = s2u(smem);

    const int tid = threadIdx.x, wid = tid >> 5, lane = tid & 31;
    const long long z = blockIdx.z;
    const int m0 = blockIdx.y * BM, n0 = blockIdx.x * BN;

    const __nv_bfloat16* pAh = Ah + z * sA + (long long)m0 * lda;
    const __nv_bfloat16* pAl = Al + z * sA + (long long)m0 * lda;
    const __nv_bfloat16* pBh = Bh + z * sB + (long long)n0 * ldb;
    const __nv_bfloat16* pBl = Bl + z * sB + (long long)n0 * ldb;

    // ---- stage loader: 128 rows x 8 x 16B chunks per matrix, XOR swizzle
    auto load_stage = [&](int slot, int k0) {
        const uint32_t st = sb + (uint32_t)slot * STAGE_BYTES;
#pragma unroll
        for (int j = 0; j < 4; j++) {
            const int i = tid + 256 * j;
            const int r = i >> 3, ch = i & 7;
            const uint32_t o = (uint32_t)r * 128 + (uint32_t)((ch ^ (r & 7)) << 4);
            const long long ga = (long long)r * lda + k0 + ch * 8;
            const long long gb = (long long)r * ldb + k0 + ch * 8;
            cpa16(st + o,          pAh + ga);
            cpa16(st + 16384 + o,  pAl + ga);
            cpa16(st + 32768 + o,  pBh + gb);
            cpa16(st + 49152 + o,  pBl + gb);
        }
    };

    // ---- warp/thread tiling
    const int warp_m = (wid & 1) * 64;       // 2 warps over M
    const int warp_n = (wid >> 1) * 32;      // 4 warps over N

    const int a_row = lane & 15;
    const int a_k   = lane >> 4;
    const int b_row = (lane & 7) | ((lane & 16) >> 1);
    const int b_k   = (lane >> 3) & 1;
    const int swzA  = a_row & 7, swzB = b_row & 7;

    uint32_t rbA[4], rbB[2];
#pragma unroll
    for (int mt = 0; mt < 4; mt++) rbA[mt] = (uint32_t)(warp_m + mt * 16 + a_row) * 128;
#pragma unroll
    for (int p = 0; p < 2; p++)    rbB[p]  = (uint32_t)(warp_n + p * 16 + b_row) * 128;

    float acc[4][4][4];
#pragma unroll
    for (int mt = 0; mt < 4; mt++)
#pragma unroll
        for (int nt = 0; nt < 4; nt++)
#pragma unroll
            for (int e = 0; e < 4; e++) acc[mt][nt][e] = 0.f;

    const int NC = K / KC;                   // >= 8 for all our shapes

    // Prologue: fill 2 of 3 slots (one always free for the in-loop load).
    load_stage(0, 0);      cpa_commit();
    load_stage(1, KC);     cpa_commit();

    for (int c = 0; c < NC; c++) {
        // chunk c resident (all-but-newest groups drained; last iter drain all)
        if (c == NC - 1) cpa_wait<0>(); else cpa_wait<1>();
        __syncthreads();   // also: every warp finished reading slot (c+2)%3

        if (c + 2 < NC) { load_stage((c + 2) % NSTAGE, (c + 2) * KC); cpa_commit(); }

        const uint32_t st = sb + (uint32_t)(c % NSTAGE) * STAGE_BYTES;
#pragma unroll
        for (int ks = 0; ks < 4; ks++) {
            const uint32_t chA = (uint32_t)(((2 * ks + a_k) ^ swzA) << 4);
            const uint32_t chB = (uint32_t)(((2 * ks + b_k) ^ swzB) << 4);

            uint32_t ah[4][4], al[4][4];
#pragma unroll
            for (int mt = 0; mt < 4; mt++) {
                ldsm4(ah[mt], st +         rbA[mt] + chA);
                ldsm4(al[mt], st + 16384 + rbA[mt] + chA);
            }
            uint32_t bh[2][4], bl[2][4];
#pragma unroll
            for (int p = 0; p < 2; p++) {
                ldsm4(bh[p], st + 32768 + rbB[p] + chB);
                ldsm4(bl[p], st + 49152 + rbB[p] + chB);
            }
            // product passes: hh, hl, lh — 16 independent MMAs between
            // successive accumulates into the same acc tile.
#pragma unroll
            for (int prod = 0; prod < 3; prod++) {
#pragma unroll
                for (int mt = 0; mt < 4; mt++)
#pragma unroll
                    for (int nt = 0; nt < 4; nt++) {
                        const uint32_t* ap = (prod == 2) ? al[mt] : ah[mt];
                        const uint32_t* bp = (prod == 1)
                            ? &bl[nt >> 1][(nt & 1) * 2]
                            : &bh[nt >> 1][(nt & 1) * 2];
                        mma_bf16(acc[mt][nt], ap, bp);
                    }
            }
        }
    }

    // ---- epilogue straight from registers
    const int r0 = m0 + warp_m + (lane >> 2);
    const int c0 = n0 + warp_n + (lane & 3) * 2;
#pragma unroll
    for (int nt = 0; nt < 4; nt++) {
        const int col = c0 + nt * 8;
        float bc0 = 0.f, bc1 = 0.f;
        if (BIAS_MODE == 1) { bc0 = bias[col]; bc1 = bias[col + 1]; }
#pragma unroll
        for (int mt = 0; mt < 4; mt++) {
#pragma unroll
            for (int half = 0; half < 2; half++) {
                const int row = r0 + mt * 16 + half * 8;
                float br = 0.f;
                if (BIAS_MODE == 2) br = bias[row];
                float x0 = acc[mt][nt][2 * half + 0];
                float x1 = acc[mt][nt][2 * half + 1];
                if (BIAS_MODE == 1) { x0 += bc0; x1 += bc1; }
                if (BIAS_MODE == 2) { x0 += br;  x1 += br;  }
                x0 *= scale; x1 *= scale;

                const long long base = z * sC + (long long)row * ldc + col;
                if (!SPLIT_OUT) {
                    *(float2*)(Cf + base) = make_float2(x0, x1);
                } else {
                    __nv_bfloat16 h0, l0, h1, l1;
                    split2(x0, h0, l0); split2(x1, h1, l1);
                    __nv_bfloat162 hh; hh.x = h0; hh.y = h1;
                    __nv_bfloat162 ll; ll.x = l0; ll.y = l1;
                    *(__nv_bfloat162*)(Ch + base) = hh;
                    *(__nv_bfloat162*)(Cl + base) = ll;
                }
            }
        }
    }
}

// ---------------- fp32 -> hi/lo bf16 elementwise split --------------------
__global__ void __launch_bounds__(256)
split_kernel(const float* __restrict__ x, __nv_bfloat16* __restrict__ h,
             __nv_bfloat16* __restrict__ l, int n4)
{
    int i = blockIdx.x * 256 + threadIdx.x;
    if (i >= n4) return;
    float4 a = ((const float4*)x)[i];
    __nv_bfloat16 h0,l0,h1,l1,h2,l2,h3,l3;
    split2(a.x, h0, l0); split2(a.y, h1, l1);
    split2(a.z, h2, l2); split2(a.w, h3, l3);
    __nv_bfloat162 p0; p0.x=h0; p0.y=h1;  __nv_bfloat162 p1; p1.x=h2; p1.y=h3;
    __nv_bfloat162 q0; q0.x=l0; q0.y=l1;  __nv_bfloat162 q1; q1.x=l2; q1.y=l3;
    ((__nv_bfloat162*)h)[2*i] = p0; ((__nv_bfloat162*)h)[2*i+1] = p1;
    ((__nv_bfloat162*)l)[2*i] = q0; ((__nv_bfloat162*)l)[2*i+1] = q1;
}

// ---------------- W [K,N] -> W^T [N,K] hi/lo bf16 --------------------------
__global__ void __launch_bounds__(256)
tsplitW(const float* __restrict__ W, __nv_bfloat16* __restrict__ Th,
        __nv_bfloat16* __restrict__ Tl)
{
    __shared__ float t[32][33];
    const int bx = blockIdx.x * 32;   // n
    const int by = blockIdx.y * 32;   // k
    const int x = threadIdx.x & 31, y = threadIdx.x >> 5;   // 32 x 8
#pragma unroll
    for (int j = 0; j < 32; j += 8)
        t[y + j][x] = W[(long long)(by + y + j) * DIM + bx + x];
    __syncthreads();
#pragma unroll
    for (int j = 0; j < 32; j += 8) {
        float v = t[x][y + j];
        __nv_bfloat16 h, l; split2(v, h, l);
        long long o = (long long)(bx + y + j) * DIM + by + x;
        Th[o] = h; Tl[o] = l;
    }
}

// ---------------- softmax rows (fp32 in) -> hi/lo bf16 P -------------------
__global__ void __launch_bounds__(256)
softmax_split(const float* __restrict__ S, __nv_bfloat16* __restrict__ Ph,
              __nv_bfloat16* __restrict__ Pl)
{
    const float* row = S + (size_t)blockIdx.x * SEQ;
    const int t = threadIdx.x;

    float v[8];
    float m = -3.4e38f;
#pragma unroll
    for (int i = 0; i < 8; i++) { v[i] = row[t + i * 256]; m = fmaxf(m, v[i]); }

    __shared__ float red[8];
#pragma unroll
    for (int o = 16; o; o >>= 1) m = fmaxf(m, __shfl_xor_sync(0xffffffffu, m, o));
    if ((t & 31) == 0) red[t >> 5] = m;
    __syncthreads();
    m = red[0];
#pragma unroll
    for (int w = 1; w < 8; w++) m = fmaxf(m, red[w]);
    __syncthreads();

    float s = 0.f;
#pragma unroll
    for (int i = 0; i < 8; i++) { v[i] = __expf(v[i] - m); s += v[i]; }
#pragma unroll
    for (int o = 16; o; o >>= 1) s += __shfl_xor_sync(0xffffffffu, s, o);
    if ((t & 31) == 0) red[t >> 5] = s;
    __syncthreads();
    s = 0.f;
#pragma unroll
    for (int w = 0; w < 8; w++) s += red[w];

    const float inv = 1.0f / s;
    const size_t rb = (size_t)blockIdx.x * SEQ;
#pragma unroll
    for (int i = 0; i < 8; i++) {
        float p = v[i] * inv;
        __nv_bfloat16 h, l; split2(p, h, l);
        Ph[rb + t + i * 256] = h;
        Pl[rb + t + i * 256] = l;
    }
}

// ===========================================================================
extern "C" void kernel_launch(void* const* d_in, const int* in_sizes, int n_in,
                              void* d_out, int out_size)
{
    const float* q  = (const float*)d_in[0];
    const float* k  = (const float*)d_in[1];
    const float* v  = (const float*)d_in[2];
    const float* Wq = (const float*)d_in[3];
    const float* bq = (const float*)d_in[4];
    const float* Wk = (const float*)d_in[5];
    const float* bk = (const float*)d_in[6];
    const float* Wv = (const float*)d_in[7];
    const float* bv = (const float*)d_in[8];
    float* out = (float*)d_out;

    __nv_bfloat16 *qh,*ql,*kh,*kl,*vh,*vl, *wqh,*wql,*wkh,*wkl,*wvh,*wvl;
    __nv_bfloat16 *qph,*qpl,*kph,*kpl,*vth,*vtl, *ph,*pl;
    float* sc;
    cudaGetSymbolAddress((void**)&qh,  g_qh);  cudaGetSymbolAddress((void**)&ql,  g_ql);
    cudaGetSymbolAddress((void**)&kh,  g_kh);  cudaGetSymbolAddress((void**)&kl,  g_kl);
    cudaGetSymbolAddress((void**)&vh,  g_vh);  cudaGetSymbolAddress((void**)&vl,  g_vl);
    cudaGetSymbolAddress((void**)&wqh, g_wqh); cudaGetSymbolAddress((void**)&wql, g_wql);
    cudaGetSymbolAddress((void**)&wkh, g_wkh); cudaGetSymbolAddress((void**)&wkl, g_wkl);
    cudaGetSymbolAddress((void**)&wvh, g_wvh); cudaGetSymbolAddress((void**)&wvl, g_wvl);
    cudaGetSymbolAddress((void**)&qph, g_qph); cudaGetSymbolAddress((void**)&qpl, g_qpl);
    cudaGetSymbolAddress((void**)&kph, g_kph); cudaGetSymbolAddress((void**)&kpl, g_kpl);
    cudaGetSymbolAddress((void**)&vth, g_vth); cudaGetSymbolAddress((void**)&vtl, g_vtl);
    cudaGetSymbolAddress((void**)&ph,  g_ph);  cudaGetSymbolAddress((void**)&pl,  g_pl);
    cudaGetSymbolAddress((void**)&sc,  g_sc);

    cudaFuncSetAttribute(gemm3<1, true>,  cudaFuncAttributeMaxDynamicSharedMemorySize, GEMM_SMEM);
    cudaFuncSetAttribute(gemm3<2, true>,  cudaFuncAttributeMaxDynamicSharedMemorySize, GEMM_SMEM);
    cudaFuncSetAttribute(gemm3<0, false>, cudaFuncAttributeMaxDynamicSharedMemorySize, GEMM_SMEM);

    const float qscale = 0.04419417382415922f;   // 1/sqrt(512)
    const int n4 = (int)(NTOK / 4);

    // 1) split inputs to hi/lo bf16
    split_kernel<<<(n4 + 255) / 256, 256>>>(q, qh, ql, n4);
    split_kernel<<<(n4 + 255) / 256, 256>>>(k, kh, kl, n4);
    split_kernel<<<(n4 + 255) / 256, 256>>>(v, vh, vl, n4);

    // 2) transpose + split weights (W[k,n] -> WT[n,k])
    tsplitW<<<dim3(16, 16), 256>>>(Wq, wqh, wql);
    tsplitW<<<dim3(16, 16), 256>>>(Wk, wkh, wkl);
    tsplitW<<<dim3(16, 16), 256>>>(Wv, wvh, wvl);

    // 3) projections
    gemm3<1, true><<<dim3(4, 128, 1), 256, GEMM_SMEM>>>(
        qh, ql, wqh, wql, bq, nullptr, qph, qpl,
        DIM, DIM, DIM, DIM, 0, 0, 0, qscale);
    gemm3<1, true><<<dim3(4, 128, 1), 256, GEMM_SMEM>>>(
        kh, kl, wkh, wkl, bk, nullptr, kph, kpl,
        DIM, DIM, DIM, DIM, 0, 0, 0, 1.0f);
    // vpT[d,t] = sum_e WvT[d,e] v[t,e] + bv[d]  -> split bf16, ldc = 16384
    gemm3<2, true><<<dim3(128, 4, 1), 256, GEMM_SMEM>>>(
        wvh, wvl, vh, vl, bv, nullptr, vth, vtl,
        DIM, DIM, DIM, MTOT, 0, 0, 0, 1.0f);

    // 4) scores: per batch S[sq,sk] = qp . kp  (fp32)
    gemm3<0, false><<<dim3(16, 16, BATCH), 256, GEMM_SMEM>>>(
        qph, qpl, kph, kpl, nullptr, sc, nullptr, nullptr,
        DIM, DIM, DIM, SEQ,
        (long long)SEQ * DIM, (long long)SEQ * DIM, (long long)SEQ * SEQ, 1.0f);

    // 5) softmax -> split bf16 P
    softmax_split<<<BATCH * SEQ, 256>>>(sc, ph, pl);

    // 6) O = P vp : B[n=d, k=s] = vpT[d, z*2048 + s]  (ldb=16384, batch stride 2048)
    gemm3<0, false><<<dim3(4, 16, BATCH), 256, GEMM_SMEM>>>(
        ph, pl, vth, vtl, nullptr, out, nullptr, nullptr,
        SEQ, SEQ, MTOT, DIM,
        (long long)SEQ * SEQ, (long long)SEQ, (long long)SEQ * DIM, 1.0f);
}

// round 13
// speedup vs baseline: 1.3701x; 1.3701x over previous
#include <cuda_runtime.h>
#include <cuda_fp16.h>
#include <cstdint>

// ===========================================================================
// AttentionGate via mma.sync fp16 split-2 GEMMs.
// (tcgen05 unavailable: harness PTX targets sm_103, not sm_103a.)
//   Per GEMM: round operand A to fp16 (err 2^-12), split operand B = bh + bl
//   (fp16 each, err 2^-22):  A*B ~= a*bh + a*bl   -> 2 MMAs (was 3 w/ bf16x3).
// Pipeline:
//   q,k -> fp16 ; v -> fp16 hi/lo ; WqT,WkT -> fp16 hi/lo ; WvT -> fp16
//   qp  = q WqT + bq          [fp16 out]          (A=q,  B=Wq split)
//   kp  = k WkT + bk          [fp16 hi/lo out]    (A=k,  B=Wk split)
//   vpT = WvT v^T + bv        [fp16 hi/lo out, (d,tok) layout] (A=WvT, B=v split)
//   S   = (qp kp^T)*scale     [fp32]              (A=qp, B=kp split)
//   P   = softmax(S)          [fp16 out]
//   O   = P vp                [fp32 -> d_out]     (A=P,  B=vpT split)
// ===========================================================================

#define BATCH 8
#define SEQ   2048
#define DIM   512
#define MTOT  (BATCH * SEQ)          // 16384
#define NTOK  ((size_t)MTOT * DIM)   // 8388608

// ---------------- scratch (__device__ globals; allocation-free) -----------
__device__ __half g_q16[NTOK], g_k16[NTOK];
__device__ __half g_vh[NTOK],  g_vl[NTOK];
__device__ __half g_wqh[DIM*DIM], g_wql[DIM*DIM];
__device__ __half g_wkh[DIM*DIM], g_wkl[DIM*DIM];
__device__ __half g_wvt[DIM*DIM];
__device__ __half g_qp16[NTOK];
__device__ __half g_kph[NTOK], g_kpl[NTOK];
__device__ __half g_vth[NTOK], g_vtl[NTOK];
__device__ float  g_sc[(size_t)BATCH * SEQ * SEQ];     // 128 MB
__device__ __half g_p16[(size_t)BATCH * SEQ * SEQ];

// ---------------- PTX helpers (sm_80-era: legal on plain sm_103) ----------
__device__ __forceinline__ uint32_t s2u(const void* p) {
    uint32_t a;
    asm("{ .reg .u64 t; cvta.to.shared.u64 t, %1; cvt.u32.u64 %0, t; }"
        : "=r"(a) : "l"(p));
    return a;
}
__device__ __forceinline__ void cpa16(uint32_t s, const void* g) {
    asm volatile("cp.async.cg.shared.global [%0], [%1], 16;" :: "r"(s), "l"(g));
}
__device__ __forceinline__ void cpa_commit() {
    asm volatile("cp.async.commit_group;" ::: "memory");
}
template <int N>
__device__ __forceinline__ void cpa_wait() {
    asm volatile("cp.async.wait_group %0;" :: "n"(N) : "memory");
}
__device__ __forceinline__ void ldsm4(uint32_t* r, uint32_t a) {
    asm volatile("ldmatrix.sync.aligned.m8n8.x4.shared.b16 {%0,%1,%2,%3}, [%4];"
        : "=r"(r[0]), "=r"(r[1]), "=r"(r[2]), "=r"(r[3]) : "r"(a));
}
__device__ __forceinline__ void mma_f16(float* d, const uint32_t* a, const uint32_t* b) {
    asm volatile(
        "mma.sync.aligned.m16n8k16.row.col.f32.f16.f16.f32 "
        "{%0,%1,%2,%3},{%4,%5,%6,%7},{%8,%9},{%0,%1,%2,%3};"
        : "+f"(d[0]), "+f"(d[1]), "+f"(d[2]), "+f"(d[3])
        : "r"(a[0]), "r"(a[1]), "r"(a[2]), "r"(a[3]), "r"(b[0]), "r"(b[1]));
}
__device__ __forceinline__ void split2h(float x, __half& h, __half& l) {
    h = __float2half_rn(x);
    l = __float2half_rn(x - __half2float(h));
}

// ===========================================================================
// mma.sync fp16 split-2 GEMM:  C[M,N] = (A * B^T + bias) * scale  (per grid.z)
//   A: [M,K] K-major fp16,  B: [N,K] K-major fp16 hi/lo pair
//   CTA tile 128x128, KC=64, 3-stage cp.async (one sync per chunk),
//   8 warps (2m x 4n), 64x32 per warp. 2 MMAs per k16 per acc tile.
//   BIAS_MODE: 0 none, 1 per-col bias[n], 2 per-row bias[m]
//   OUT_MODE:  0 fp32 Cf, 1 fp16 Ch, 2 fp16 hi/lo Ch+Cl
// ===========================================================================
#define BM 128
#define BN 128
#define KC 64
#define STAGE_BYTES 49152            // A 16K | Bh 16K | Bl 16K
#define NSTAGE 3
#define GEMM_SMEM   (NSTAGE * STAGE_BYTES)

template <int BIAS_MODE, int OUT_MODE>
__global__ void __launch_bounds__(256, 1)
gemm2(const __half* __restrict__ A,
      const __half* __restrict__ Bh, const __half* __restrict__ Bl,
      const float* __restrict__ bias,
      float* __restrict__ Cf, __half* __restrict__ Ch, __half* __restrict__ Cl,
      int K, int lda, int ldb, int ldc,
      long long sA, long long sB, long long sC, float scale)
{
    extern __shared__ __align__(1024) char smem[];
    const uint32_t sb = s2u(smem);

    const int tid = threadIdx.x, wid = tid >> 5, lane = tid & 31;
    const long long z = blockIdx.z;
    const int m0 = blockIdx.y * BM, n0 = blockIdx.x * BN;

    const __half* pA  = A  + z * sA + (long long)m0 * lda;
    const __half* pBh = Bh + z * sB + (long long)n0 * ldb;
    const __half* pBl = Bl + z * sB + (long long)n0 * ldb;

    // ---- stage loader: 128 rows x 8 x 16B chunks per matrix, XOR swizzle
    auto load_stage = [&](int slot, int k0) {
        const uint32_t st = sb + (uint32_t)slot * STAGE_BYTES;
#pragma unroll
        for (int j = 0; j < 4; j++) {
            const int i = tid + 256 * j;
            const int r = i >> 3, ch = i & 7;
            const uint32_t o = (uint32_t)r * 128 + (uint32_t)((ch ^ (r & 7)) << 4);
            const long long ga = (long long)r * lda + k0 + ch * 8;
            const long long gb = (long long)r * ldb + k0 + ch * 8;
            cpa16(st + o,          pA  + ga);
            cpa16(st + 16384 + o,  pBh + gb);
            cpa16(st + 32768 + o,  pBl + gb);
        }
    };

    // ---- warp/thread tiling
    const int warp_m = (wid & 1) * 64;       // 2 warps over M
    const int warp_n = (wid >> 1) * 32;      // 4 warps over N

    const int a_row = lane & 15;
    const int a_k   = lane >> 4;
    const int b_row = (lane & 7) | ((lane & 16) >> 1);
    const int b_k   = (lane >> 3) & 1;
    const int swzA  = a_row & 7, swzB = b_row & 7;

    uint32_t rbA[4], rbB[2];
#pragma unroll
    for (int mt = 0; mt < 4; mt++) rbA[mt] = (uint32_t)(warp_m + mt * 16 + a_row) * 128;
#pragma unroll
    for (int p = 0; p < 2; p++)    rbB[p]  = (uint32_t)(warp_n + p * 16 + b_row) * 128;

    float acc[4][4][4];
#pragma unroll
    for (int mt = 0; mt < 4; mt++)
#pragma unroll
        for (int nt = 0; nt < 4; nt++)
#pragma unroll
            for (int e = 0; e < 4; e++) acc[mt][nt][e] = 0.f;

    const int NC = K / KC;

    load_stage(0, 0);      cpa_commit();
    load_stage(1, KC);     cpa_commit();

    for (int c = 0; c < NC; c++) {
        if (c == NC - 1) cpa_wait<0>(); else cpa_wait<1>();
        __syncthreads();

        if (c + 2 < NC) { load_stage((c + 2) % NSTAGE, (c + 2) * KC); cpa_commit(); }

        const uint32_t st = sb + (uint32_t)(c % NSTAGE) * STAGE_BYTES;
#pragma unroll
        for (int ks = 0; ks < 4; ks++) {
            const uint32_t chA = (uint32_t)(((2 * ks + a_k) ^ swzA) << 4);
            const uint32_t chB = (uint32_t)(((2 * ks + b_k) ^ swzB) << 4);

            uint32_t af[4][4];
#pragma unroll
            for (int mt = 0; mt < 4; mt++)
                ldsm4(af[mt], st + rbA[mt] + chA);
            uint32_t bh[2][4], bl[2][4];
#pragma unroll
            for (int p = 0; p < 2; p++) {
                ldsm4(bh[p], st + 16384 + rbB[p] + chB);
                ldsm4(bl[p], st + 32768 + rbB[p] + chB);
            }
            // 2 product passes: a*bh, a*bl — 16 independent MMAs between
            // successive accumulates into the same acc tile.
#pragma unroll
            for (int prod = 0; prod < 2; prod++) {
#pragma unroll
                for (int mt = 0; mt < 4; mt++)
#pragma unroll
                    for (int nt = 0; nt < 4; nt++) {
                        const uint32_t* bp = (prod == 0)
                            ? &bh[nt >> 1][(nt & 1) * 2]
                            : &bl[nt >> 1][(nt & 1) * 2];
                        mma_f16(acc[mt][nt], af[mt], bp);
                    }
            }
        }
    }

    // ---- epilogue straight from registers
    const int r0 = m0 + warp_m + (lane >> 2);
    const int c0 = n0 + warp_n + (lane & 3) * 2;
#pragma unroll
    for (int nt = 0; nt < 4; nt++) {
        const int col = c0 + nt * 8;
        float bc0 = 0.f, bc1 = 0.f;
        if (BIAS_MODE == 1) { bc0 = bias[col]; bc1 = bias[col + 1]; }
#pragma unroll
        for (int mt = 0; mt < 4; mt++) {
#pragma unroll
            for (int half = 0; half < 2; half++) {
                const int row = r0 + mt * 16 + half * 8;
                float br = 0.f;
                if (BIAS_MODE == 2) br = bias[row];
                float x0 = acc[mt][nt][2 * half + 0];
                float x1 = acc[mt][nt][2 * half + 1];
                if (BIAS_MODE == 1) { x0 += bc0; x1 += bc1; }
                if (BIAS_MODE == 2) { x0 += br;  x1 += br;  }
                x0 *= scale; x1 *= scale;

                const long long base = z * sC + (long long)row * ldc + col;
                if (OUT_MODE == 0) {
                    *(float2*)(Cf + base) = make_float2(x0, x1);
                } else if (OUT_MODE == 1) {
                    __half2 hh; hh.x = __float2half_rn(x0); hh.y = __float2half_rn(x1);
                    *(__half2*)(Ch + base) = hh;
                } else {
                    __half h0, l0, h1, l1;
                    split2h(x0, h0, l0); split2h(x1, h1, l1);
                    __half2 hh; hh.x = h0; hh.y = h1;
                    __half2 ll; ll.x = l0; ll.y = l1;
                    *(__half2*)(Ch + base) = hh;
                    *(__half2*)(Cl + base) = ll;
                }
            }
        }
    }
}

// ---------------- fp32 -> fp16 round (single) ------------------------------
__global__ void __launch_bounds__(256)
round_kernel(const float* __restrict__ x, __half* __restrict__ h, int n4)
{
    int i = blockIdx.x * 256 + threadIdx.x;
    if (i >= n4) return;
    float4 a = ((const float4*)x)[i];
    __half2 p0; p0.x = __float2half_rn(a.x); p0.y = __float2half_rn(a.y);
    __half2 p1; p1.x = __float2half_rn(a.z); p1.y = __float2half_rn(a.w);
    ((__half2*)h)[2*i] = p0; ((__half2*)h)[2*i+1] = p1;
}

// ---------------- fp32 -> fp16 hi/lo split ---------------------------------
__global__ void __launch_bounds__(256)
splitv_kernel(const float* __restrict__ x, __half* __restrict__ h,
              __half* __restrict__ l, int n4)
{
    int i = blockIdx.x * 256 + threadIdx.x;
    if (i >= n4) return;
    float4 a = ((const float4*)x)[i];
    __half h0,l0,h1,l1,h2,l2,h3,l3;
    split2h(a.x, h0, l0); split2h(a.y, h1, l1);
    split2h(a.z, h2, l2); split2h(a.w, h3, l3);
    __half2 p0; p0.x=h0; p0.y=h1;  __half2 p1; p1.x=h2; p1.y=h3;
    __half2 q0; q0.x=l0; q0.y=l1;  __half2 q1; q1.x=l2; q1.y=l3;
    ((__half2*)h)[2*i] = p0; ((__half2*)h)[2*i+1] = p1;
    ((__half2*)l)[2*i] = q0; ((__half2*)l)[2*i+1] = q1;
}

// ---------------- W [K,N] -> W^T [N,K] fp16 hi/lo --------------------------
__global__ void __launch_bounds__(256)
tsplitW(const float* __restrict__ W, __half* __restrict__ Th,
        __half* __restrict__ Tl)
{
    __shared__ float t[32][33];
    const int bx = blockIdx.x * 32;   // n
    const int by = blockIdx.y * 32;   // k
    const int x = threadIdx.x & 31, y = threadIdx.x >> 5;
#pragma unroll
    for (int j = 0; j < 32; j += 8)
        t[y + j][x] = W[(long long)(by + y + j) * DIM + bx + x];
    __syncthreads();
#pragma unroll
    for (int j = 0; j < 32; j += 8) {
        float v = t[x][y + j];
        __half h, l; split2h(v, h, l);
        long long o = (long long)(bx + y + j) * DIM + by + x;
        Th[o] = h; Tl[o] = l;
    }
}

// ---------------- W [K,N] -> W^T [N,K] fp16 single -------------------------
__global__ void __launch_bounds__(256)
troundW(const float* __restrict__ W, __half* __restrict__ T)
{
    __shared__ float t[32][33];
    const int bx = blockIdx.x * 32;
    const int by = blockIdx.y * 32;
    const int x = threadIdx.x & 31, y = threadIdx.x >> 5;
#pragma unroll
    for (int j = 0; j < 32; j += 8)
        t[y + j][x] = W[(long long)(by + y + j) * DIM + bx + x];
    __syncthreads();
#pragma unroll
    for (int j = 0; j < 32; j += 8) {
        long long o = (long long)(bx + y + j) * DIM + by + x;
        T[o] = __float2half_rn(t[x][y + j]);
    }
}

// ---------------- softmax rows (fp32 in) -> fp16 P --------------------------
__global__ void __launch_bounds__(256)
softmax_h(const float* __restrict__ S, __half* __restrict__ P)
{
    const float* row = S + (size_t)blockIdx.x * SEQ;
    const int t = threadIdx.x;

    float v[8];
    float m = -3.4e38f;
#pragma unroll
    for (int i = 0; i < 8; i++) { v[i] = row[t + i * 256]; m = fmaxf(m, v[i]); }

    __shared__ float red[8];
#pragma unroll
    for (int o = 16; o; o >>= 1) m = fmaxf(m, __shfl_xor_sync(0xffffffffu, m, o));
    if ((t & 31) == 0) red[t >> 5] = m;
    __syncthreads();
    m = red[0];
#pragma unroll
    for (int w = 1; w < 8; w++) m = fmaxf(m, red[w]);
    __syncthreads();

    float s = 0.f;
#pragma unroll
    for (int i = 0; i < 8; i++) { v[i] = __expf(v[i] - m); s += v[i]; }
#pragma unroll
    for (int o = 16; o; o >>= 1) s += __shfl_xor_sync(0xffffffffu, s, o);
    if ((t & 31) == 0) red[t >> 5] = s;
    __syncthreads();
    s = 0.f;
#pragma unroll
    for (int w = 0; w < 8; w++) s += red[w];

    const float inv = 1.0f / s;
    const size_t rb = (size_t)blockIdx.x * SEQ;
#pragma unroll
    for (int i = 0; i < 8; i++)
        P[rb + t + i * 256] = __float2half_rn(v[i] * inv);
}

// ===========================================================================
extern "C" void kernel_launch(void* const* d_in, const int* in_sizes, int n_in,
                              void* d_out, int out_size)
{
    const float* q  = (const float*)d_in[0];
    const float* k  = (const float*)d_in[1];
    const float* v  = (const float*)d_in[2];
    const float* Wq = (const float*)d_in[3];
    const float* bq = (const float*)d_in[4];
    const float* Wk = (const float*)d_in[5];
    const float* bk = (const float*)d_in[6];
    const float* Wv = (const float*)d_in[7];
    const float* bv = (const float*)d_in[8];
    float* out = (float*)d_out;

    __half *q16,*k16,*vh,*vl, *wqh,*wql,*wkh,*wkl,*wvt;
    __half *qp16,*kph,*kpl,*vth,*vtl,*p16;
    float* sc;
    cudaGetSymbolAddress((void**)&q16, g_q16); cudaGetSymbolAddress((void**)&k16, g_k16);
    cudaGetSymbolAddress((void**)&vh,  g_vh);  cudaGetSymbolAddress((void**)&vl,  g_vl);
    cudaGetSymbolAddress((void**)&wqh, g_wqh); cudaGetSymbolAddress((void**)&wql, g_wql);
    cudaGetSymbolAddress((void**)&wkh, g_wkh); cudaGetSymbolAddress((void**)&wkl, g_wkl);
    cudaGetSymbolAddress((void**)&wvt, g_wvt);
    cudaGetSymbolAddress((void**)&qp16, g_qp16);
    cudaGetSymbolAddress((void**)&kph, g_kph); cudaGetSymbolAddress((void**)&kpl, g_kpl);
    cudaGetSymbolAddress((void**)&vth, g_vth); cudaGetSymbolAddress((void**)&vtl, g_vtl);
    cudaGetSymbolAddress((void**)&p16, g_p16);
    cudaGetSymbolAddress((void**)&sc,  g_sc);

    cudaFuncSetAttribute(gemm2<1, 1>, cudaFuncAttributeMaxDynamicSharedMemorySize, GEMM_SMEM);
    cudaFuncSetAttribute(gemm2<1, 2>, cudaFuncAttributeMaxDynamicSharedMemorySize, GEMM_SMEM);
    cudaFuncSetAttribute(gemm2<2, 2>, cudaFuncAttributeMaxDynamicSharedMemorySize, GEMM_SMEM);
    cudaFuncSetAttribute(gemm2<0, 0>, cudaFuncAttributeMaxDynamicSharedMemorySize, GEMM_SMEM);

    const float qscale = 0.04419417382415922f;   // 1/sqrt(512), applied to scores
    const int n4 = (int)(NTOK / 4);

    // 1) conversions
    round_kernel<<<(n4 + 255) / 256, 256>>>(q, q16, n4);
    round_kernel<<<(n4 + 255) / 256, 256>>>(k, k16, n4);
    splitv_kernel<<<(n4 + 255) / 256, 256>>>(v, vh, vl, n4);
    tsplitW<<<dim3(16, 16), 256>>>(Wq, wqh, wql);
    tsplitW<<<dim3(16, 16), 256>>>(Wk, wkh, wkl);
    troundW<<<dim3(16, 16), 256>>>(Wv, wvt);

    // 2) projections
    // qp[t,d] = q . WqT + bq   -> fp16 single
    gemm2<1, 1><<<dim3(4, 128, 1), 256, GEMM_SMEM>>>(
        q16, wqh, wql, bq, nullptr, qp16, nullptr,
        DIM, DIM, DIM, DIM, 0, 0, 0, 1.0f);
    // kp[t,d] = k . WkT + bk   -> fp16 hi/lo
    gemm2<1, 2><<<dim3(4, 128, 1), 256, GEMM_SMEM>>>(
        k16, wkh, wkl, bk, nullptr, kph, kpl,
        DIM, DIM, DIM, DIM, 0, 0, 0, 1.0f);
    // vpT[d,t] = WvT . v^T + bv[d]  -> fp16 hi/lo, ldc = 16384 (token-major rows)
    gemm2<2, 2><<<dim3(128, 4, 1), 256, GEMM_SMEM>>>(
        wvt, vh, vl, bv, nullptr, vth, vtl,
        DIM, DIM, DIM, MTOT, 0, 0, 0, 1.0f);

    // 3) scores: per batch S = (qp . kp^T) * qscale  (fp32)
    gemm2<0, 0><<<dim3(16, 16, BATCH), 256, GEMM_SMEM>>>(
        qp16, kph, kpl, nullptr, sc, nullptr, nullptr,
        DIM, DIM, DIM, SEQ,
        (long long)SEQ * DIM, (long long)SEQ * DIM, (long long)SEQ * SEQ, qscale);

    // 4) softmax -> fp16 P
    softmax_h<<<BATCH * SEQ, 256>>>(sc, p16);

    // 5) O = P vp : B[n=d, k=s] = vpT[d, z*2048 + s]  (ldb=16384, batch stride 2048)
    gemm2<0, 0><<<dim3(4, 16, BATCH), 256, GEMM_SMEM>>>(
        p16, vth, vtl, nullptr, out, nullptr, nullptr,
        SEQ, SEQ, MTOT, DIM,
        (long long)SEQ * SEQ, (long long)SEQ, (long long)SEQ * DIM, 1.0f);
}

// round 14
// speedup vs baseline: 1.7999x; 1.3137x over previous
#include <cuda_runtime.h>
#include <cuda_fp16.h>
#include <cstdint>

// ===========================================================================
// AttentionGate via mma.sync fp16 GEMMs, mixed split-2 / single precision.
// (tcgen05 unavailable: harness PTX targets sm_103, not sm_103a.)
//   Projections: A fp16 single, B = bh+bl fp16 split  -> 2 MMAs  (accuracy)
//   Attention  : A fp16 single, B fp16 single         -> 1 MMA   (speed)
// Pipeline:
//   q,k -> fp16 ; v -> fp16 hi/lo ; WqT,WkT -> fp16 hi/lo ; WvT -> fp16
//   qp  = q WqT + bq          [fp16]
//   kp  = k WkT + bk          [fp16]
//   vpT = WvT v^T + bv        [fp16, (d, tokens) layout]
//   S   = (qp kp^T)*scale     [fp16]
//   P   = softmax(S)          [fp16]
//   O   = P vp                [fp32 -> d_out]
// ===========================================================================

#define BATCH 8
#define SEQ   2048
#define DIM   512
#define MTOT  (BATCH * SEQ)          // 16384
#define NTOK  ((size_t)MTOT * DIM)   // 8388608

// ---------------- scratch (__device__ globals; allocation-free) -----------
__device__ __half g_q16[NTOK], g_k16[NTOK];
__device__ __half g_vh[NTOK],  g_vl[NTOK];
__device__ __half g_wqh[DIM*DIM], g_wql[DIM*DIM];
__device__ __half g_wkh[DIM*DIM], g_wkl[DIM*DIM];
__device__ __half g_wvt[DIM*DIM];
__device__ __half g_qp16[NTOK];
__device__ __half g_kp16[NTOK];
__device__ __half g_vt16[NTOK];
__device__ __half g_sch[(size_t)BATCH * SEQ * SEQ];    // 64 MB, fp16 scores
__device__ __half g_p16[(size_t)BATCH * SEQ * SEQ];

// ---------------- PTX helpers (sm_80-era: legal on plain sm_103) ----------
__device__ __forceinline__ uint32_t s2u(const void* p) {
    uint32_t a;
    asm("{ .reg .u64 t; cvta.to.shared.u64 t, %1; cvt.u32.u64 %0, t; }"
        : "=r"(a) : "l"(p));
    return a;
}
__device__ __forceinline__ void cpa16(uint32_t s, const void* g) {
    asm volatile("cp.async.cg.shared.global [%0], [%1], 16;" :: "r"(s), "l"(g));
}
__device__ __forceinline__ void cpa_commit() {
    asm volatile("cp.async.commit_group;" ::: "memory");
}
template <int N>
__device__ __forceinline__ void cpa_wait() {
    asm volatile("cp.async.wait_group %0;" :: "n"(N) : "memory");
}
__device__ __forceinline__ void ldsm4(uint32_t* r, uint32_t a) {
    asm volatile("ldmatrix.sync.aligned.m8n8.x4.shared.b16 {%0,%1,%2,%3}, [%4];"
        : "=r"(r[0]), "=r"(r[1]), "=r"(r[2]), "=r"(r[3]) : "r"(a));
}
__device__ __forceinline__ void mma_f16(float* d, const uint32_t* a, const uint32_t* b) {
    asm volatile(
        "mma.sync.aligned.m16n8k16.row.col.f32.f16.f16.f32 "
        "{%0,%1,%2,%3},{%4,%5,%6,%7},{%8,%9},{%0,%1,%2,%3};"
        : "+f"(d[0]), "+f"(d[1]), "+f"(d[2]), "+f"(d[3])
        : "r"(a[0]), "r"(a[1]), "r"(a[2]), "r"(a[3]), "r"(b[0]), "r"(b[1]));
}
__device__ __forceinline__ void split2h(float x, __half& h, __half& l) {
    h = __float2half_rn(x);
    l = __float2half_rn(x - __half2float(h));
}

// ===========================================================================
// mma.sync fp16 GEMM:  C[M,N] = (A * B^T + bias) * scale   (per grid.z batch)
//   A: [M,K] K-major fp16,  B: [N,K] K-major fp16 (+ optional lo part)
//   CTA tile 128x128, KC=64, 3-stage cp.async (one sync per chunk),
//   8 warps (2m x 4n), 64x32 per warp.
//   NPROD: 1 -> C = A*Bh ; 2 -> C = A*Bh + A*Bl (split-precision B)
//   BIAS_MODE: 0 none, 1 per-col bias[n], 2 per-row bias[m]
//   OUT_MODE:  0 fp32 Cf, 1 fp16 Ch
// ===========================================================================
#define BM 128
#define BN 128
#define KC 64
#define NSTAGE 3

template <int BIAS_MODE, int OUT_MODE, int NPROD>
__global__ void __launch_bounds__(256, 1)
gemmx(const __half* __restrict__ A,
      const __half* __restrict__ Bh, const __half* __restrict__ Bl,
      const float* __restrict__ bias,
      float* __restrict__ Cf, __half* __restrict__ Ch,
      int K, int lda, int ldb, int ldc,
      long long sA, long long sB, long long sC, float scale)
{
    constexpr uint32_t STB = (NPROD == 2) ? 49152u : 32768u;  // A | Bh | [Bl]

    extern __shared__ __align__(1024) char smem[];
    const uint32_t sb = s2u(smem);

    const int tid = threadIdx.x, wid = tid >> 5, lane = tid & 31;
    const long long z = blockIdx.z;
    const int m0 = blockIdx.y * BM, n0 = blockIdx.x * BN;

    const __half* pA  = A  + z * sA + (long long)m0 * lda;
    const __half* pBh = Bh + z * sB + (long long)n0 * ldb;
    const __half* pBl = (NPROD == 2) ? (Bl + z * sB + (long long)n0 * ldb) : nullptr;

    // ---- stage loader: 128 rows x 8 x 16B chunks per matrix, XOR swizzle
    auto load_stage = [&](int slot, int k0) {
        const uint32_t st = sb + (uint32_t)slot * STB;
#pragma unroll
        for (int j = 0; j < 4; j++) {
            const int i = tid + 256 * j;
            const int r = i >> 3, ch = i & 7;
            const uint32_t o = (uint32_t)r * 128 + (uint32_t)((ch ^ (r & 7)) << 4);
            const long long ga = (long long)r * lda + k0 + ch * 8;
            const long long gb = (long long)r * ldb + k0 + ch * 8;
            cpa16(st + o,          pA  + ga);
            cpa16(st + 16384 + o,  pBh + gb);
            if (NPROD == 2) cpa16(st + 32768 + o, pBl + gb);
        }
    };

    // ---- warp/thread tiling
    const int warp_m = (wid & 1) * 64;       // 2 warps over M
    const int warp_n = (wid >> 1) * 32;      // 4 warps over N

    const int a_row = lane & 15;
    const int a_k   = lane >> 4;
    const int b_row = (lane & 7) | ((lane & 16) >> 1);
    const int b_k   = (lane >> 3) & 1;
    const int swzA  = a_row & 7, swzB = b_row & 7;

    uint32_t rbA[4], rbB[2];
#pragma unroll
    for (int mt = 0; mt < 4; mt++) rbA[mt] = (uint32_t)(warp_m + mt * 16 + a_row) * 128;
#pragma unroll
    for (int p = 0; p < 2; p++)    rbB[p]  = (uint32_t)(warp_n + p * 16 + b_row) * 128;

    float acc[4][4][4];
#pragma unroll
    for (int mt = 0; mt < 4; mt++)
#pragma unroll
        for (int nt = 0; nt < 4; nt++)
#pragma unroll
            for (int e = 0; e < 4; e++) acc[mt][nt][e] = 0.f;

    const int NC = K / KC;

    load_stage(0, 0);      cpa_commit();
    load_stage(1, KC);     cpa_commit();

    for (int c = 0; c < NC; c++) {
        if (c == NC - 1) cpa_wait<0>(); else cpa_wait<1>();
        __syncthreads();

        if (c + 2 < NC) { load_stage((c + 2) % NSTAGE, (c + 2) * KC); cpa_commit(); }

        const uint32_t st = sb + (uint32_t)(c % NSTAGE) * STB;
#pragma unroll
        for (int ks = 0; ks < 4; ks++) {
            const uint32_t chA = (uint32_t)(((2 * ks + a_k) ^ swzA) << 4);
            const uint32_t chB = (uint32_t)(((2 * ks + b_k) ^ swzB) << 4);

            uint32_t af[4][4];
#pragma unroll
            for (int mt = 0; mt < 4; mt++)
                ldsm4(af[mt], st + rbA[mt] + chA);
            uint32_t bh[2][4], bl[2][4];
#pragma unroll
            for (int p = 0; p < 2; p++) {
                ldsm4(bh[p], st + 16384 + rbB[p] + chB);
                if (NPROD == 2) ldsm4(bl[p], st + 32768 + rbB[p] + chB);
            }
#pragma unroll
            for (int prod = 0; prod < NPROD; prod++) {
#pragma unroll
                for (int mt = 0; mt < 4; mt++)
#pragma unroll
                    for (int nt = 0; nt < 4; nt++) {
                        const uint32_t* bp = (prod == 0)
                            ? &bh[nt >> 1][(nt & 1) * 2]
                            : &bl[nt >> 1][(nt & 1) * 2];
                        mma_f16(acc[mt][nt], af[mt], bp);
                    }
            }
        }
    }

    // ---- epilogue straight from registers
    const int r0 = m0 + warp_m + (lane >> 2);
    const int c0 = n0 + warp_n + (lane & 3) * 2;
#pragma unroll
    for (int nt = 0; nt < 4; nt++) {
        const int col = c0 + nt * 8;
        float bc0 = 0.f, bc1 = 0.f;
        if (BIAS_MODE == 1) { bc0 = bias[col]; bc1 = bias[col + 1]; }
#pragma unroll
        for (int mt = 0; mt < 4; mt++) {
#pragma unroll
            for (int half = 0; half < 2; half++) {
                const int row = r0 + mt * 16 + half * 8;
                float br = 0.f;
                if (BIAS_MODE == 2) br = bias[row];
                float x0 = acc[mt][nt][2 * half + 0];
                float x1 = acc[mt][nt][2 * half + 1];
                if (BIAS_MODE == 1) { x0 += bc0; x1 += bc1; }
                if (BIAS_MODE == 2) { x0 += br;  x1 += br;  }
                x0 *= scale; x1 *= scale;

                const long long base = z * sC + (long long)row * ldc + col;
                if (OUT_MODE == 0) {
                    *(float2*)(Cf + base) = make_float2(x0, x1);
                } else {
                    __half2 hh; hh.x = __float2half_rn(x0); hh.y = __float2half_rn(x1);
                    *(__half2*)(Ch + base) = hh;
                }
            }
        }
    }
}

// ---------------- fp32 -> fp16 round (single) ------------------------------
__global__ void __launch_bounds__(256)
round_kernel(const float* __restrict__ x, __half* __restrict__ h, int n4)
{
    int i = blockIdx.x * 256 + threadIdx.x;
    if (i >= n4) return;
    float4 a = ((const float4*)x)[i];
    __half2 p0; p0.x = __float2half_rn(a.x); p0.y = __float2half_rn(a.y);
    __half2 p1; p1.x = __float2half_rn(a.z); p1.y = __float2half_rn(a.w);
    ((__half2*)h)[2*i] = p0; ((__half2*)h)[2*i+1] = p1;
}

// ---------------- fp32 -> fp16 hi/lo split ---------------------------------
__global__ void __launch_bounds__(256)
splitv_kernel(const float* __restrict__ x, __half* __restrict__ h,
              __half* __restrict__ l, int n4)
{
    int i = blockIdx.x * 256 + threadIdx.x;
    if (i >= n4) return;
    float4 a = ((const float4*)x)[i];
    __half h0,l0,h1,l1,h2,l2,h3,l3;
    split2h(a.x, h0, l0); split2h(a.y, h1, l1);
    split2h(a.z, h2, l2); split2h(a.w, h3, l3);
    __half2 p0; p0.x=h0; p0.y=h1;  __half2 p1; p1.x=h2; p1.y=h3;
    __half2 q0; q0.x=l0; q0.y=l1;  __half2 q1; q1.x=l2; q1.y=l3;
    ((__half2*)h)[2*i] = p0; ((__half2*)h)[2*i+1] = p1;
    ((__half2*)l)[2*i] = q0; ((__half2*)l)[2*i+1] = q1;
}

// ---------------- W [K,N] -> W^T [N,K] fp16 hi/lo --------------------------
__global__ void __launch_bounds__(256)
tsplitW(const float* __restrict__ W, __half* __restrict__ Th,
        __half* __restrict__ Tl)
{
    __shared__ float t[32][33];
    const int bx = blockIdx.x * 32;   // n
    const int by = blockIdx.y * 32;   // k
    const int x = threadIdx.x & 31, y = threadIdx.x >> 5;
#pragma unroll
    for (int j = 0; j < 32; j += 8)
        t[y + j][x] = W[(long long)(by + y + j) * DIM + bx + x];
    __syncthreads();
#pragma unroll
    for (int j = 0; j < 32; j += 8) {
        float v = t[x][y + j];
        __half h, l; split2h(v, h, l);
        long long o = (long long)(bx + y + j) * DIM + by + x;
        Th[o] = h; Tl[o] = l;
    }
}

// ---------------- W [K,N] -> W^T [N,K] fp16 single -------------------------
__global__ void __launch_bounds__(256)
troundW(const float* __restrict__ W, __half* __restrict__ T)
{
    __shared__ float t[32][33];
    const int bx = blockIdx.x * 32;
    const int by = blockIdx.y * 32;
    const int x = threadIdx.x & 31, y = threadIdx.x >> 5;
#pragma unroll
    for (int j = 0; j < 32; j += 8)
        t[y + j][x] = W[(long long)(by + y + j) * DIM + bx + x];
    __syncthreads();
#pragma unroll
    for (int j = 0; j < 32; j += 8) {
        long long o = (long long)(bx + y + j) * DIM + by + x;
        T[o] = __float2half_rn(t[x][y + j]);
    }
}

// ---------------- softmax rows (fp16 in) -> fp16 P --------------------------
__global__ void __launch_bounds__(256)
softmax_h(const __half* __restrict__ S, __half* __restrict__ P)
{
    const __half* row = S + (size_t)blockIdx.x * SEQ;
    const int t = threadIdx.x;

    float v[8];
    float m = -3.4e38f;
#pragma unroll
    for (int i = 0; i < 8; i++) {
        v[i] = __half2float(row[t + i * 256]);
        m = fmaxf(m, v[i]);
    }

    __shared__ float red[8];
#pragma unroll
    for (int o = 16; o; o >>= 1) m = fmaxf(m, __shfl_xor_sync(0xffffffffu, m, o));
    if ((t & 31) == 0) red[t >> 5] = m;
    __syncthreads();
    m = red[0];
#pragma unroll
    for (int w = 1; w < 8; w++) m = fmaxf(m, red[w]);
    __syncthreads();

    float s = 0.f;
#pragma unroll
    for (int i = 0; i < 8; i++) { v[i] = __expf(v[i] - m); s += v[i]; }
#pragma unroll
    for (int o = 16; o; o >>= 1) s += __shfl_xor_sync(0xffffffffu, s, o);
    if ((t & 31) == 0) red[t >> 5] = s;
    __syncthreads();
    s = 0.f;
#pragma unroll
    for (int w = 0; w < 8; w++) s += red[w];

    const float inv = 1.0f / s;
    const size_t rb = (size_t)blockIdx.x * SEQ;
#pragma unroll
    for (int i = 0; i < 8; i++)
        P[rb + t + i * 256] = __float2half_rn(v[i] * inv);
}

// ===========================================================================
extern "C" void kernel_launch(void* const* d_in, const int* in_sizes, int n_in,
                              void* d_out, int out_size)
{
    const float* q  = (const float*)d_in[0];
    const float* k  = (const float*)d_in[1];
    const float* v  = (const float*)d_in[2];
    const float* Wq = (const float*)d_in[3];
    const float* bq = (const float*)d_in[4];
    const float* Wk = (const float*)d_in[5];
    const float* bk = (const float*)d_in[6];
    const float* Wv = (const float*)d_in[7];
    const float* bv = (const float*)d_in[8];
    float* out = (float*)d_out;

    __half *q16,*k16,*vh,*vl, *wqh,*wql,*wkh,*wkl,*wvt;
    __half *qp16,*kp16,*vt16,*sch,*p16;
    cudaGetSymbolAddress((void**)&q16, g_q16); cudaGetSymbolAddress((void**)&k16, g_k16);
    cudaGetSymbolAddress((void**)&vh,  g_vh);  cudaGetSymbolAddress((void**)&vl,  g_vl);
    cudaGetSymbolAddress((void**)&wqh, g_wqh); cudaGetSymbolAddress((void**)&wql, g_wql);
    cudaGetSymbolAddress((void**)&wkh, g_wkh); cudaGetSymbolAddress((void**)&wkl, g_wkl);
    cudaGetSymbolAddress((void**)&wvt, g_wvt);
    cudaGetSymbolAddress((void**)&qp16, g_qp16);
    cudaGetSymbolAddress((void**)&kp16, g_kp16);
    cudaGetSymbolAddress((void**)&vt16, g_vt16);
    cudaGetSymbolAddress((void**)&sch, g_sch);
    cudaGetSymbolAddress((void**)&p16, g_p16);

    const int SM2 = NSTAGE * 49152;   // split-B GEMMs
    const int SM1 = NSTAGE * 32768;   // single-B GEMMs
    cudaFuncSetAttribute(gemmx<1, 1, 2>, cudaFuncAttributeMaxDynamicSharedMemorySize, SM2);
    cudaFuncSetAttribute(gemmx<2, 1, 2>, cudaFuncAttributeMaxDynamicSharedMemorySize, SM2);
    cudaFuncSetAttribute(gemmx<0, 1, 1>, cudaFuncAttributeMaxDynamicSharedMemorySize, SM1);
    cudaFuncSetAttribute(gemmx<0, 0, 1>, cudaFuncAttributeMaxDynamicSharedMemorySize, SM1);

    const float qscale = 0.04419417382415922f;   // 1/sqrt(512), applied to scores
    const int n4 = (int)(NTOK / 4);

    // 1) conversions
    round_kernel<<<(n4 + 255) / 256, 256>>>(q, q16, n4);
    round_kernel<<<(n4 + 255) / 256, 256>>>(k, k16, n4);
    splitv_kernel<<<(n4 + 255) / 256, 256>>>(v, vh, vl, n4);
    tsplitW<<<dim3(16, 16), 256>>>(Wq, wqh, wql);
    tsplitW<<<dim3(16, 16), 256>>>(Wk, wkh, wkl);
    troundW<<<dim3(16, 16), 256>>>(Wv, wvt);

    // 2) projections (split-B, 2 MMAs)
    gemmx<1, 1, 2><<<dim3(4, 128, 1), 256, SM2>>>(
        q16, wqh, wql, bq, nullptr, qp16,
        DIM, DIM, DIM, DIM, 0, 0, 0, 1.0f);
    gemmx<1, 1, 2><<<dim3(4, 128, 1), 256, SM2>>>(
        k16, wkh, wkl, bk, nullptr, kp16,
        DIM, DIM, DIM, DIM, 0, 0, 0, 1.0f);
    // vpT[d,t] = WvT . v^T + bv[d]  -> fp16, ldc = 16384 (token-major rows)
    gemmx<2, 1, 2><<<dim3(128, 4, 1), 256, SM2>>>(
        wvt, vh, vl, bv, nullptr, vt16,
        DIM, DIM, DIM, MTOT, 0, 0, 0, 1.0f);

    // 3) scores: per batch S = (qp . kp^T) * qscale -> fp16 (single-B, 1 MMA)
    gemmx<0, 1, 1><<<dim3(16, 16, BATCH), 256, SM1>>>(
        qp16, kp16, nullptr, nullptr, nullptr, sch,
        DIM, DIM, DIM, SEQ,
        (long long)SEQ * DIM, (long long)SEQ * DIM, (long long)SEQ * SEQ, qscale);

    // 4) softmax -> fp16 P
    softmax_h<<<BATCH * SEQ, 256>>>(sch, p16);

    // 5) O = P vp : B[n=d, k=s] = vpT[d, z*2048 + s]  (single-B, 1 MMA)
    gemmx<0, 0, 1><<<dim3(4, 16, BATCH), 256, SM1>>>(
        p16, vt16, nullptr, nullptr, out, nullptr,
        SEQ, SEQ, MTOT, DIM,
        (long long)SEQ * SEQ, (long long)SEQ, (long long)SEQ * DIM, 1.0f);
}

// round 15
// speedup vs baseline: 2.0555x; 1.1420x over previous
#include <cuda_runtime.h>
#include <cuda_fp16.h>
#include <cstdint>

// ===========================================================================
// AttentionGate via mma.sync fp16 GEMMs — single-precision fp16 everywhere
// (R15: dropped all hi/lo splits; tensor FLOPs at workload minimum 94.5 GF).
// (tcgen05 unavailable: harness PTX targets sm_103, not sm_103a.)
// Pipeline:
//   q,k,v -> fp16 (one batched kernel) ; WqT,WkT,WvT -> fp16 (one batched kernel)
//   qp  = q WqT + bq          [fp16]
//   kp  = k WkT + bk          [fp16]
//   vpT = WvT v^T + bv        [fp16, (d, tokens) layout]
//   S   = (qp kp^T)*scale     [fp16]
//   P   = softmax(S)          [fp16]
//   O   = P vp                [fp32 -> d_out]
// ===========================================================================

#define BATCH 8
#define SEQ   2048
#define DIM   512
#define MTOT  (BATCH * SEQ)          // 16384
#define NTOK  ((size_t)MTOT * DIM)   // 8388608

// ---------------- scratch (__device__ globals; allocation-free) -----------
__device__ __half g_q16[NTOK], g_k16[NTOK], g_v16[NTOK];
__device__ __half g_wqt[DIM*DIM], g_wkt[DIM*DIM], g_wvt[DIM*DIM];
__device__ __half g_qp16[NTOK], g_kp16[NTOK], g_vt16[NTOK];
__device__ __half g_sch[(size_t)BATCH * SEQ * SEQ];    // 64 MB fp16 scores
__device__ __half g_p16[(size_t)BATCH * SEQ * SEQ];

// ---------------- PTX helpers (sm_80-era: legal on plain sm_103) ----------
__device__ __forceinline__ uint32_t s2u(const void* p) {
    uint32_t a;
    asm("{ .reg .u64 t; cvta.to.shared.u64 t, %1; cvt.u32.u64 %0, t; }"
        : "=r"(a) : "l"(p));
    return a;
}
__device__ __forceinline__ void cpa16(uint32_t s, const void* g) {
    asm volatile("cp.async.cg.shared.global [%0], [%1], 16;" :: "r"(s), "l"(g));
}
__device__ __forceinline__ void cpa_commit() {
    asm volatile("cp.async.commit_group;" ::: "memory");
}
template <int N>
__device__ __forceinline__ void cpa_wait() {
    asm volatile("cp.async.wait_group %0;" :: "n"(N) : "memory");
}
__device__ __forceinline__ void ldsm4(uint32_t* r, uint32_t a) {
    asm volatile("ldmatrix.sync.aligned.m8n8.x4.shared.b16 {%0,%1,%2,%3}, [%4];"
        : "=r"(r[0]), "=r"(r[1]), "=r"(r[2]), "=r"(r[3]) : "r"(a));
}
__device__ __forceinline__ void mma_f16(float* d, const uint32_t* a, const uint32_t* b) {
    asm volatile(
        "mma.sync.aligned.m16n8k16.row.col.f32.f16.f16.f32 "
        "{%0,%1,%2,%3},{%4,%5,%6,%7},{%8,%9},{%0,%1,%2,%3};"
        : "+f"(d[0]), "+f"(d[1]), "+f"(d[2]), "+f"(d[3])
        : "r"(a[0]), "r"(a[1]), "r"(a[2]), "r"(a[3]), "r"(b[0]), "r"(b[1]));
}

// ===========================================================================
// mma.sync fp16 GEMM:  C[M,N] = (A * B^T + bias) * scale   (per grid.z batch)
//   A: [M,K] K-major fp16,  B: [N,K] K-major fp16
//   CTA tile 128x128, KC=64, 3-stage cp.async (one sync per chunk),
//   8 warps (2m x 4n), 64x32 per warp, 1 MMA per k16 per acc tile.
//   BIAS_MODE: 0 none, 1 per-col bias[n], 2 per-row bias[m]
//   OUT_MODE:  0 fp32 Cf, 1 fp16 Ch
// ===========================================================================
#define BM 128
#define BN 128
#define KC 64
#define NSTAGE 3
#define STB 32768u                    // A 16K | B 16K per stage
#define GEMM_SMEM (NSTAGE * STB)      // 96 KB

template <int BIAS_MODE, int OUT_MODE>
__global__ void __launch_bounds__(256, 1)
gemmx(const __half* __restrict__ A, const __half* __restrict__ B,
      const float* __restrict__ bias,
      float* __restrict__ Cf, __half* __restrict__ Ch,
      int K, int lda, int ldb, int ldc,
      long long sA, long long sB, long long sC, float scale)
{
    extern __shared__ __align__(1024) char smem[];
    const uint32_t sb = s2u(smem);

    const int tid = threadIdx.x, wid = tid >> 5, lane = tid & 31;
    const long long z = blockIdx.z;
    const int m0 = blockIdx.y * BM, n0 = blockIdx.x * BN;

    const __half* pA = A + z * sA + (long long)m0 * lda;
    const __half* pB = B + z * sB + (long long)n0 * ldb;

    // ---- stage loader: 128 rows x 8 x 16B chunks per matrix, XOR swizzle
    auto load_stage = [&](int slot, int k0) {
        const uint32_t st = sb + (uint32_t)slot * STB;
#pragma unroll
        for (int j = 0; j < 4; j++) {
            const int i = tid + 256 * j;
            const int r = i >> 3, ch = i & 7;
            const uint32_t o = (uint32_t)r * 128 + (uint32_t)((ch ^ (r & 7)) << 4);
            cpa16(st + o,         pA + (long long)r * lda + k0 + ch * 8);
            cpa16(st + 16384 + o, pB + (long long)r * ldb + k0 + ch * 8);
        }
    };

    // ---- warp/thread tiling
    const int warp_m = (wid & 1) * 64;       // 2 warps over M
    const int warp_n = (wid >> 1) * 32;      // 4 warps over N

    const int a_row = lane & 15;
    const int a_k   = lane >> 4;
    const int b_row = (lane & 7) | ((lane & 16) >> 1);
    const int b_k   = (lane >> 3) & 1;
    const int swzA  = a_row & 7, swzB = b_row & 7;

    uint32_t rbA[4], rbB[2];
#pragma unroll
    for (int mt = 0; mt < 4; mt++) rbA[mt] = (uint32_t)(warp_m + mt * 16 + a_row) * 128;
#pragma unroll
    for (int p = 0; p < 2; p++)    rbB[p]  = (uint32_t)(warp_n + p * 16 + b_row) * 128;

    float acc[4][4][4];
#pragma unroll
    for (int mt = 0; mt < 4; mt++)
#pragma unroll
        for (int nt = 0; nt < 4; nt++)
#pragma unroll
            for (int e = 0; e < 4; e++) acc[mt][nt][e] = 0.f;

    const int NC = K / KC;

    load_stage(0, 0);      cpa_commit();
    load_stage(1, KC);     cpa_commit();

    for (int c = 0; c < NC; c++) {
        if (c == NC - 1) cpa_wait<0>(); else cpa_wait<1>();
        __syncthreads();

        if (c + 2 < NC) { load_stage((c + 2) % NSTAGE, (c + 2) * KC); cpa_commit(); }

        const uint32_t st = sb + (uint32_t)(c % NSTAGE) * STB;
#pragma unroll
        for (int ks = 0; ks < 4; ks++) {
            const uint32_t chA = (uint32_t)(((2 * ks + a_k) ^ swzA) << 4);
            const uint32_t chB = (uint32_t)(((2 * ks + b_k) ^ swzB) << 4);

            uint32_t af[4][4];
#pragma unroll
            for (int mt = 0; mt < 4; mt++)
                ldsm4(af[mt], st + rbA[mt] + chA);
            uint32_t bf[2][4];
#pragma unroll
            for (int p = 0; p < 2; p++)
                ldsm4(bf[p], st + 16384 + rbB[p] + chB);
#pragma unroll
            for (int mt = 0; mt < 4; mt++)
#pragma unroll
                for (int nt = 0; nt < 4; nt++)
                    mma_f16(acc[mt][nt], af[mt], &bf[nt >> 1][(nt & 1) * 2]);
        }
    }

    // ---- epilogue straight from registers
    const int r0 = m0 + warp_m + (lane >> 2);
    const int c0 = n0 + warp_n + (lane & 3) * 2;
#pragma unroll
    for (int nt = 0; nt < 4; nt++) {
        const int col = c0 + nt * 8;
        float bc0 = 0.f, bc1 = 0.f;
        if (BIAS_MODE == 1) { bc0 = bias[col]; bc1 = bias[col + 1]; }
#pragma unroll
        for (int mt = 0; mt < 4; mt++) {
#pragma unroll
            for (int half = 0; half < 2; half++) {
                const int row = r0 + mt * 16 + half * 8;
                float br = 0.f;
                if (BIAS_MODE == 2) br = bias[row];
                float x0 = acc[mt][nt][2 * half + 0];
                float x1 = acc[mt][nt][2 * half + 1];
                if (BIAS_MODE == 1) { x0 += bc0; x1 += bc1; }
                if (BIAS_MODE == 2) { x0 += br;  x1 += br;  }
                x0 *= scale; x1 *= scale;

                const long long base = z * sC + (long long)row * ldc + col;
                if (OUT_MODE == 0) {
                    *(float2*)(Cf + base) = make_float2(x0, x1);
                } else {
                    __half2 hh; hh.x = __float2half_rn(x0); hh.y = __float2half_rn(x1);
                    *(__half2*)(Ch + base) = hh;
                }
            }
        }
    }
}

// ---------------- fp32 -> fp16 round, batched over q/k/v -------------------
__global__ void __launch_bounds__(256)
round3_kernel(const float* __restrict__ x0, __half* __restrict__ h0,
              const float* __restrict__ x1, __half* __restrict__ h1,
              const float* __restrict__ x2, __half* __restrict__ h2, int n4)
{
    const float* x = (blockIdx.y == 0) ? x0 : (blockIdx.y == 1) ? x1 : x2;
    __half*      h = (blockIdx.y == 0) ? h0 : (blockIdx.y == 1) ? h1 : h2;
    int i = blockIdx.x * 256 + threadIdx.x;
    if (i >= n4) return;
    float4 a = ((const float4*)x)[i];
    __half2 p0; p0.x = __float2half_rn(a.x); p0.y = __float2half_rn(a.y);
    __half2 p1; p1.x = __float2half_rn(a.z); p1.y = __float2half_rn(a.w);
    ((__half2*)h)[2*i] = p0; ((__half2*)h)[2*i+1] = p1;
}

// ---------------- W [K,N] -> W^T [N,K] fp16, batched over 3 weights --------
__global__ void __launch_bounds__(256)
troundW3(const float* __restrict__ W0, __half* __restrict__ T0,
         const float* __restrict__ W1, __half* __restrict__ T1,
         const float* __restrict__ W2, __half* __restrict__ T2)
{
    const float* W = (blockIdx.z == 0) ? W0 : (blockIdx.z == 1) ? W1 : W2;
    __half*      T = (blockIdx.z == 0) ? T0 : (blockIdx.z == 1) ? T1 : T2;

    __shared__ float t[32][33];
    const int bx = blockIdx.x * 32;   // n
    const int by = blockIdx.y * 32;   // k
    const int x = threadIdx.x & 31, y = threadIdx.x >> 5;
#pragma unroll
    for (int j = 0; j < 32; j += 8)
        t[y + j][x] = W[(long long)(by + y + j) * DIM + bx + x];
    __syncthreads();
#pragma unroll
    for (int j = 0; j < 32; j += 8) {
        long long o = (long long)(bx + y + j) * DIM + by + x;
        T[o] = __float2half_rn(t[x][y + j]);
    }
}

// ---------------- softmax rows (fp16 in) -> fp16 P --------------------------
__global__ void __launch_bounds__(256)
softmax_h(const __half* __restrict__ S, __half* __restrict__ P)
{
    const __half* row = S + (size_t)blockIdx.x * SEQ;
    const int t = threadIdx.x;

    float v[8];
    float m = -3.4e38f;
#pragma unroll
    for (int i = 0; i < 8; i++) {
        v[i] = __half2float(row[t + i * 256]);
        m = fmaxf(m, v[i]);
    }

    __shared__ float red[8];
#pragma unroll
    for (int o = 16; o; o >>= 1) m = fmaxf(m, __shfl_xor_sync(0xffffffffu, m, o));
    if ((t & 31) == 0) red[t >> 5] = m;
    __syncthreads();
    m = red[0];
#pragma unroll
    for (int w = 1; w < 8; w++) m = fmaxf(m, red[w]);
    __syncthreads();

    float s = 0.f;
#pragma unroll
    for (int i = 0; i < 8; i++) { v[i] = __expf(v[i] - m); s += v[i]; }
#pragma unroll
    for (int o = 16; o; o >>= 1) s += __shfl_xor_sync(0xffffffffu, s, o);
    if ((t & 31) == 0) red[t >> 5] = s;
    __syncthreads();
    s = 0.f;
#pragma unroll
    for (int w = 0; w < 8; w++) s += red[w];

    const float inv = 1.0f / s;
    const size_t rb = (size_t)blockIdx.x * SEQ;
#pragma unroll
    for (int i = 0; i < 8; i++)
        P[rb + t + i * 256] = __float2half_rn(v[i] * inv);
}

// ===========================================================================
extern "C" void kernel_launch(void* const* d_in, const int* in_sizes, int n_in,
                              void* d_out, int out_size)
{
    const float* q  = (const float*)d_in[0];
    const float* k  = (const float*)d_in[1];
    const float* v  = (const float*)d_in[2];
    const float* Wq = (const float*)d_in[3];
    const float* bq = (const float*)d_in[4];
    const float* Wk = (const float*)d_in[5];
    const float* bk = (const float*)d_in[6];
    const float* Wv = (const float*)d_in[7];
    const float* bv = (const float*)d_in[8];
    float* out = (float*)d_out;

    __half *q16,*k16,*v16, *wqt,*wkt,*wvt, *qp16,*kp16,*vt16, *sch,*p16;
    cudaGetSymbolAddress((void**)&q16, g_q16);
    cudaGetSymbolAddress((void**)&k16, g_k16);
    cudaGetSymbolAddress((void**)&v16, g_v16);
    cudaGetSymbolAddress((void**)&wqt, g_wqt);
    cudaGetSymbolAddress((void**)&wkt, g_wkt);
    cudaGetSymbolAddress((void**)&wvt, g_wvt);
    cudaGetSymbolAddress((void**)&qp16, g_qp16);
    cudaGetSymbolAddress((void**)&kp16, g_kp16);
    cudaGetSymbolAddress((void**)&vt16, g_vt16);
    cudaGetSymbolAddress((void**)&sch, g_sch);
    cudaGetSymbolAddress((void**)&p16, g_p16);

    cudaFuncSetAttribute(gemmx<1, 1>, cudaFuncAttributeMaxDynamicSharedMemorySize, GEMM_SMEM);
    cudaFuncSetAttribute(gemmx<2, 1>, cudaFuncAttributeMaxDynamicSharedMemorySize, GEMM_SMEM);
    cudaFuncSetAttribute(gemmx<0, 1>, cudaFuncAttributeMaxDynamicSharedMemorySize, GEMM_SMEM);
    cudaFuncSetAttribute(gemmx<0, 0>, cudaFuncAttributeMaxDynamicSharedMemorySize, GEMM_SMEM);

    const float qscale = 0.04419417382415922f;   // 1/sqrt(512), applied to scores
    const int n4 = (int)(NTOK / 4);

    // 1) conversions (2 batched launches)
    round3_kernel<<<dim3((n4 + 255) / 256, 3), 256>>>(q, q16, k, k16, v, v16, n4);
    troundW3<<<dim3(16, 16, 3), 256>>>(Wq, wqt, Wk, wkt, Wv, wvt);

    // 2) projections (single fp16, 1 MMA per k16)
    gemmx<1, 1><<<dim3(4, 128, 1), 256, GEMM_SMEM>>>(
        q16, wqt, bq, nullptr, qp16, DIM, DIM, DIM, DIM, 0, 0, 0, 1.0f);
    gemmx<1, 1><<<dim3(4, 128, 1), 256, GEMM_SMEM>>>(
        k16, wkt, bk, nullptr, kp16, DIM, DIM, DIM, DIM, 0, 0, 0, 1.0f);
    // vpT[d,t] = WvT . v^T + bv[d]  -> fp16, ldc = 16384 (token-major rows)
    gemmx<2, 1><<<dim3(128, 4, 1), 256, GEMM_SMEM>>>(
        wvt, v16, bv, nullptr, vt16, DIM, DIM, DIM, MTOT, 0, 0, 0, 1.0f);

    // 3) scores: per batch S = (qp . kp^T) * qscale -> fp16
    gemmx<0, 1><<<dim3(16, 16, BATCH), 256, GEMM_SMEM>>>(
        qp16, kp16, nullptr, nullptr, sch,
        DIM, DIM, DIM, SEQ,
        (long long)SEQ * DIM, (long long)SEQ * DIM, (long long)SEQ * SEQ, qscale);

    // 4) softmax -> fp16 P
    softmax_h<<<BATCH * SEQ, 256>>>(sch, p16);

    // 5) O = P vp : B[n=d, k=s] = vpT[d, z*2048 + s]
    gemmx<0, 0><<<dim3(4, 16, BATCH), 256, GEMM_SMEM>>>(
        p16, vt16, nullptr, out, nullptr,
        SEQ, SEQ, MTOT, DIM,
        (long long)SEQ * SEQ, (long long)SEQ, (long long)SEQ * DIM, 1.0f);
}

// round 16
// speedup vs baseline: 2.0953x; 1.0194x over previous
#include <cuda_runtime.h>
#include <cuda_fp16.h>
#include <cstdint>

// ===========================================================================
// AttentionGate via mma.sync fp16 GEMMs — single fp16, software-pipelined.
// (tcgen05 unavailable: harness PTX targets sm_103, not sm_103a.)
// R16: register double-buffered ldmatrix frags + cross-chunk frag prefetch
//      (ncu showed tensor=36% -> latency-bound, not pipe-bound).
// Pipeline:
//   q,k,v -> fp16 ; WqT,WkT,WvT -> fp16
//   qp = q WqT + bq ; kp = k WkT + bk ; vpT = WvT v^T + bv
//   S  = (qp kp^T)*scale ; P = softmax(S) ; O = P vp
// ===========================================================================

#define BATCH 8
#define SEQ   2048
#define DIM   512
#define MTOT  (BATCH * SEQ)          // 16384
#define NTOK  ((size_t)MTOT * DIM)   // 8388608

// ---------------- scratch (__device__ globals; allocation-free) -----------
__device__ __half g_q16[NTOK], g_k16[NTOK], g_v16[NTOK];
__device__ __half g_wqt[DIM*DIM], g_wkt[DIM*DIM], g_wvt[DIM*DIM];
__device__ __half g_qp16[NTOK], g_kp16[NTOK], g_vt16[NTOK];
__device__ __half g_sch[(size_t)BATCH * SEQ * SEQ];    // 64 MB fp16 scores
__device__ __half g_p16[(size_t)BATCH * SEQ * SEQ];

// ---------------- PTX helpers (sm_80-era: legal on plain sm_103) ----------
__device__ __forceinline__ uint32_t s2u(const void* p) {
    uint32_t a;
    asm("{ .reg .u64 t; cvta.to.shared.u64 t, %1; cvt.u32.u64 %0, t; }"
        : "=r"(a) : "l"(p));
    return a;
}
__device__ __forceinline__ void cpa16(uint32_t s, const void* g) {
    asm volatile("cp.async.cg.shared.global [%0], [%1], 16;" :: "r"(s), "l"(g));
}
__device__ __forceinline__ void cpa_commit() {
    asm volatile("cp.async.commit_group;" ::: "memory");
}
template <int N>
__device__ __forceinline__ void cpa_wait() {
    asm volatile("cp.async.wait_group %0;" :: "n"(N) : "memory");
}
__device__ __forceinline__ void ldsm4(uint32_t* r, uint32_t a) {
    asm volatile("ldmatrix.sync.aligned.m8n8.x4.shared.b16 {%0,%1,%2,%3}, [%4];"
        : "=r"(r[0]), "=r"(r[1]), "=r"(r[2]), "=r"(r[3]) : "r"(a));
}
__device__ __forceinline__ void mma_f16(float* d, const uint32_t* a, const uint32_t* b) {
    asm volatile(
        "mma.sync.aligned.m16n8k16.row.col.f32.f16.f16.f32 "
        "{%0,%1,%2,%3},{%4,%5,%6,%7},{%8,%9},{%0,%1,%2,%3};"
        : "+f"(d[0]), "+f"(d[1]), "+f"(d[2]), "+f"(d[3])
        : "r"(a[0]), "r"(a[1]), "r"(a[2]), "r"(a[3]), "r"(b[0]), "r"(b[1]));
}

// ===========================================================================
// mma.sync fp16 GEMM:  C[M,N] = (A * B^T + bias) * scale   (per grid.z batch)
//   CTA tile 128x128, KC=64, 3-stage cp.async, 8 warps (2m x 4n), 64x32/warp.
//   Register-level software pipeline: frags for k-step ks+1 (or next chunk's
//   ks=0) are loaded before the MMAs of k-step ks execute.
// ===========================================================================
#define BM 128
#define BN 128
#define KC 64
#define NSTAGE 3
#define STB 32768u                    // A 16K | B 16K per stage
#define GEMM_SMEM (NSTAGE * STB)      // 96 KB

template <int BIAS_MODE, int OUT_MODE>
__global__ void __launch_bounds__(256, 1)
gemmx(const __half* __restrict__ A, const __half* __restrict__ B,
      const float* __restrict__ bias,
      float* __restrict__ Cf, __half* __restrict__ Ch,
      int K, int lda, int ldb, int ldc,
      long long sA, long long sB, long long sC, float scale)
{
    extern __shared__ __align__(1024) char smem[];
    const uint32_t sb = s2u(smem);

    const int tid = threadIdx.x, wid = tid >> 5, lane = tid & 31;
    const long long z = blockIdx.z;
    const int m0 = blockIdx.y * BM, n0 = blockIdx.x * BN;

    const __half* pA = A + z * sA + (long long)m0 * lda;
    const __half* pB = B + z * sB + (long long)n0 * ldb;

    // ---- stage loader: 128 rows x 8 x 16B chunks per matrix, XOR swizzle
    auto load_stage = [&](int slot, int k0) {
        const uint32_t st = sb + (uint32_t)slot * STB;
#pragma unroll
        for (int j = 0; j < 4; j++) {
            const int i = tid + 256 * j;
            const int r = i >> 3, ch = i & 7;
            const uint32_t o = (uint32_t)r * 128 + (uint32_t)((ch ^ (r & 7)) << 4);
            cpa16(st + o,         pA + (long long)r * lda + k0 + ch * 8);
            cpa16(st + 16384 + o, pB + (long long)r * ldb + k0 + ch * 8);
        }
    };

    // ---- warp/thread tiling
    const int warp_m = (wid & 1) * 64;       // 2 warps over M
    const int warp_n = (wid >> 1) * 32;      // 4 warps over N

    const int a_row = lane & 15;
    const int a_k   = lane >> 4;
    const int b_row = (lane & 7) | ((lane & 16) >> 1);
    const int b_k   = (lane >> 3) & 1;
    const int swzA  = a_row & 7, swzB = b_row & 7;

    uint32_t rbA[4], rbB[2];
#pragma unroll
    for (int mt = 0; mt < 4; mt++) rbA[mt] = (uint32_t)(warp_m + mt * 16 + a_row) * 128;
#pragma unroll
    for (int p = 0; p < 2; p++)    rbB[p]  = (uint32_t)(warp_n + p * 16 + b_row) * 128;

    // frags for one k16 step: af[4][4], bf[2][4]; double-buffered
    uint32_t af[2][4][4], bf[2][2][4];

    auto load_frags = [&](uint32_t st, int ks, int buf) {
        const uint32_t chA = (uint32_t)(((2 * ks + a_k) ^ swzA) << 4);
        const uint32_t chB = (uint32_t)(((2 * ks + b_k) ^ swzB) << 4);
#pragma unroll
        for (int mt = 0; mt < 4; mt++)
            ldsm4(af[buf][mt], st + rbA[mt] + chA);
#pragma unroll
        for (int p = 0; p < 2; p++)
            ldsm4(bf[buf][p], st + 16384 + rbB[p] + chB);
    };

    float acc[4][4][4];
#pragma unroll
    for (int mt = 0; mt < 4; mt++)
#pragma unroll
        for (int nt = 0; nt < 4; nt++)
#pragma unroll
            for (int e = 0; e < 4; e++) acc[mt][nt][e] = 0.f;

    const int NC = K / KC;                   // >= 8 for all shapes here

    // Prologue: fill 2 of 3 slots; make chunk 0 resident; preload its ks=0 frags.
    load_stage(0, 0);      cpa_commit();
    load_stage(1, KC);     cpa_commit();
    cpa_wait<1>();
    __syncthreads();
    load_frags(sb, 0, 0);

    for (int c = 0; c < NC; c++) {
        const uint32_t st = sb + (uint32_t)(c % NSTAGE) * STB;
#pragma unroll
        for (int ks = 0; ks < 4; ks++) {
            const int cur = ks & 1, nxt = cur ^ 1;
            if (ks < 3) {
                load_frags(st, ks + 1, nxt);           // prefetch next k-step
            } else if (c + 1 < NC) {
                // chunk boundary: chunk c+1 resident after full drain
                cpa_wait<0>();
                __syncthreads();                        // slot (c+2)%3 free
                if (c + 2 < NC) { load_stage((c + 2) % NSTAGE, (c + 2) * KC); cpa_commit(); }
                load_frags(sb + (uint32_t)((c + 1) % NSTAGE) * STB, 0, nxt);
            }
            // MMAs for this k-step overlap the LDSMs just issued
#pragma unroll
            for (int mt = 0; mt < 4; mt++)
#pragma unroll
                for (int nt = 0; nt < 4; nt++)
                    mma_f16(acc[mt][nt], af[cur][mt], &bf[cur][nt >> 1][(nt & 1) * 2]);
        }
    }

    // ---- epilogue straight from registers
    const int r0 = m0 + warp_m + (lane >> 2);
    const int c0 = n0 + warp_n + (lane & 3) * 2;
#pragma unroll
    for (int nt = 0; nt < 4; nt++) {
        const int col = c0 + nt * 8;
        float bc0 = 0.f, bc1 = 0.f;
        if (BIAS_MODE == 1) { bc0 = bias[col]; bc1 = bias[col + 1]; }
#pragma unroll
        for (int mt = 0; mt < 4; mt++) {
#pragma unroll
            for (int half = 0; half < 2; half++) {
                const int row = r0 + mt * 16 + half * 8;
                float br = 0.f;
                if (BIAS_MODE == 2) br = bias[row];
                float x0 = acc[mt][nt][2 * half + 0];
                float x1 = acc[mt][nt][2 * half + 1];
                if (BIAS_MODE == 1) { x0 += bc0; x1 += bc1; }
                if (BIAS_MODE == 2) { x0 += br;  x1 += br;  }
                x0 *= scale; x1 *= scale;

                const long long base = z * sC + (long long)row * ldc + col;
                if (OUT_MODE == 0) {
                    *(float2*)(Cf + base) = make_float2(x0, x1);
                } else {
                    __half2 hh; hh.x = __float2half_rn(x0); hh.y = __float2half_rn(x1);
                    *(__half2*)(Ch + base) = hh;
                }
            }
        }
    }
}

// ---------------- fp32 -> fp16 round, batched over q/k/v -------------------
__global__ void __launch_bounds__(256)
round3_kernel(const float* __restrict__ x0, __half* __restrict__ h0,
              const float* __restrict__ x1, __half* __restrict__ h1,
              const float* __restrict__ x2, __half* __restrict__ h2, int n4)
{
    const float* x = (blockIdx.y == 0) ? x0 : (blockIdx.y == 1) ? x1 : x2;
    __half*      h = (blockIdx.y == 0) ? h0 : (blockIdx.y == 1) ? h1 : h2;
    int i = blockIdx.x * 256 + threadIdx.x;
    if (i >= n4) return;
    float4 a = ((const float4*)x)[i];
    __half2 p0; p0.x = __float2half_rn(a.x); p0.y = __float2half_rn(a.y);
    __half2 p1; p1.x = __float2half_rn(a.z); p1.y = __float2half_rn(a.w);
    ((__half2*)h)[2*i] = p0; ((__half2*)h)[2*i+1] = p1;
}

// ---------------- W [K,N] -> W^T [N,K] fp16, batched over 3 weights --------
__global__ void __launch_bounds__(256)
troundW3(const float* __restrict__ W0, __half* __restrict__ T0,
         const float* __restrict__ W1, __half* __restrict__ T1,
         const float* __restrict__ W2, __half* __restrict__ T2)
{
    const float* W = (blockIdx.z == 0) ? W0 : (blockIdx.z == 1) ? W1 : W2;
    __half*      T = (blockIdx.z == 0) ? T0 : (blockIdx.z == 1) ? T1 : T2;

    __shared__ float t[32][33];
    const int bx = blockIdx.x * 32;   // n
    const int by = blockIdx.y * 32;   // k
    const int x = threadIdx.x & 31, y = threadIdx.x >> 5;
#pragma unroll
    for (int j = 0; j < 32; j += 8)
        t[y + j][x] = W[(long long)(by + y + j) * DIM + bx + x];
    __syncthreads();
#pragma unroll
    for (int j = 0; j < 32; j += 8) {
        long long o = (long long)(bx + y + j) * DIM + by + x;
        T[o] = __float2half_rn(t[x][y + j]);
    }
}

// ---------------- softmax rows (fp16 in) -> fp16 P --------------------------
__global__ void __launch_bounds__(256)
softmax_h(const __half* __restrict__ S, __half* __restrict__ P)
{
    const __half* row = S + (size_t)blockIdx.x * SEQ;
    const int t = threadIdx.x;

    float v[8];
    float m = -3.4e38f;
#pragma unroll
    for (int i = 0; i < 8; i++) {
        v[i] = __half2float(row[t + i * 256]);
        m = fmaxf(m, v[i]);
    }

    __shared__ float red[8];
#pragma unroll
    for (int o = 16; o; o >>= 1) m = fmaxf(m, __shfl_xor_sync(0xffffffffu, m, o));
    if ((t & 31) == 0) red[t >> 5] = m;
    __syncthreads();
    m = red[0];
#pragma unroll
    for (int w = 1; w < 8; w++) m = fmaxf(m, red[w]);
    __syncthreads();

    float s = 0.f;
#pragma unroll
    for (int i = 0; i < 8; i++) { v[i] = __expf(v[i] - m); s += v[i]; }
#pragma unroll
    for (int o = 16; o; o >>= 1) s += __shfl_xor_sync(0xffffffffu, s, o);
    if ((t & 31) == 0) red[t >> 5] = s;
    __syncthreads();
    s = 0.f;
#pragma unroll
    for (int w = 0; w < 8; w++) s += red[w];

    const float inv = 1.0f / s;
    const size_t rb = (size_t)blockIdx.x * SEQ;
#pragma unroll
    for (int i = 0; i < 8; i++)
        P[rb + t + i * 256] = __float2half_rn(v[i] * inv);
}

// ===========================================================================
extern "C" void kernel_launch(void* const* d_in, const int* in_sizes, int n_in,
                              void* d_out, int out_size)
{
    const float* q  = (const float*)d_in[0];
    const float* k  = (const float*)d_in[1];
    const float* v  = (const float*)d_in[2];
    const float* Wq = (const float*)d_in[3];
    const float* bq = (const float*)d_in[4];
    const float* Wk = (const float*)d_in[5];
    const float* bk = (const float*)d_in[6];
    const float* Wv = (const float*)d_in[7];
    const float* bv = (const float*)d_in[8];
    float* out = (float*)d_out;

    __half *q16,*k16,*v16, *wqt,*wkt,*wvt, *qp16,*kp16,*vt16, *sch,*p16;
    cudaGetSymbolAddress((void**)&q16, g_q16);
    cudaGetSymbolAddress((void**)&k16, g_k16);
    cudaGetSymbolAddress((void**)&v16, g_v16);
    cudaGetSymbolAddress((void**)&wqt, g_wqt);
    cudaGetSymbolAddress((void**)&wkt, g_wkt);
    cudaGetSymbolAddress((void**)&wvt, g_wvt);
    cudaGetSymbolAddress((void**)&qp16, g_qp16);
    cudaGetSymbolAddress((void**)&kp16, g_kp16);
    cudaGetSymbolAddress((void**)&vt16, g_vt16);
    cudaGetSymbolAddress((void**)&sch, g_sch);
    cudaGetSymbolAddress((void**)&p16, g_p16);

    cudaFuncSetAttribute(gemmx<1, 1>, cudaFuncAttributeMaxDynamicSharedMemorySize, GEMM_SMEM);
    cudaFuncSetAttribute(gemmx<2, 1>, cudaFuncAttributeMaxDynamicSharedMemorySize, GEMM_SMEM);
    cudaFuncSetAttribute(gemmx<0, 1>, cudaFuncAttributeMaxDynamicSharedMemorySize, GEMM_SMEM);
    cudaFuncSetAttribute(gemmx<0, 0>, cudaFuncAttributeMaxDynamicSharedMemorySize, GEMM_SMEM);

    const float qscale = 0.04419417382415922f;   // 1/sqrt(512), applied to scores
    const int n4 = (int)(NTOK / 4);

    // 1) conversions (2 batched launches)
    round3_kernel<<<dim3((n4 + 255) / 256, 3), 256>>>(q, q16, k, k16, v, v16, n4);
    troundW3<<<dim3(16, 16, 3), 256>>>(Wq, wqt, Wk, wkt, Wv, wvt);

    // 2) projections
    gemmx<1, 1><<<dim3(4, 128, 1), 256, GEMM_SMEM>>>(
        q16, wqt, bq, nullptr, qp16, DIM, DIM, DIM, DIM, 0, 0, 0, 1.0f);
    gemmx<1, 1><<<dim3(4, 128, 1), 256, GEMM_SMEM>>>(
        k16, wkt, bk, nullptr, kp16, DIM, DIM, DIM, DIM, 0, 0, 0, 1.0f);
    // vpT[d,t] = WvT . v^T + bv[d]  -> fp16, ldc = 16384 (token-major rows)
    gemmx<2, 1><<<dim3(128, 4, 1), 256, GEMM_SMEM>>>(
        wvt, v16, bv, nullptr, vt16, DIM, DIM, DIM, MTOT, 0, 0, 0, 1.0f);

    // 3) scores: per batch S = (qp . kp^T) * qscale -> fp16
    gemmx<0, 1><<<dim3(16, 16, BATCH), 256, GEMM_SMEM>>>(
        qp16, kp16, nullptr, nullptr, sch,
        DIM, DIM, DIM, SEQ,
        (long long)SEQ * DIM, (long long)SEQ * DIM, (long long)SEQ * SEQ, qscale);

    // 4) softmax -> fp16 P
    softmax_h<<<BATCH * SEQ, 256>>>(sch, p16);

    // 5) O = P vp : B[n=d, k=s] = vpT[d, z*2048 + s]
    gemmx<0, 0><<<dim3(4, 16, BATCH), 256, GEMM_SMEM>>>(
        p16, vt16, nullptr, out, nullptr,
        SEQ, SEQ, MTOT, DIM,
        (long long)SEQ * SEQ, (long long)SEQ, (long long)SEQ * DIM, 1.0f);
}

// round 17
// speedup vs baseline: 2.3100x; 1.1025x over previous
#include <cuda_runtime.h>
#include <cuda_fp16.h>
#include <cstdint>

// ===========================================================================
// AttentionGate via mma.sync fp16 GEMMs — single fp16.
// R17: CTA tile 128x256, 512 threads (16 warps -> 4 warps/SMSP, was 2).
//      ncu R15/R16: tensor ~37%, occ 12%, issue 20% -> issue-width bound.
// (tcgen05 unavailable: harness PTX targets sm_103, not sm_103a.)
// Pipeline:
//   q,k,v -> fp16 ; WqT,WkT,WvT -> fp16
//   qp = q WqT + bq ; kp = k WkT + bk ; vpT = WvT v^T + bv
//   S  = (qp kp^T)*scale ; P = softmax(S) ; O = P vp
// ===========================================================================

#define BATCH 8
#define SEQ   2048
#define DIM   512
#define MTOT  (BATCH * SEQ)          // 16384
#define NTOK  ((size_t)MTOT * DIM)   // 8388608

// ---------------- scratch (__device__ globals; allocation-free) -----------
__device__ __half g_q16[NTOK], g_k16[NTOK], g_v16[NTOK];
__device__ __half g_wqt[DIM*DIM], g_wkt[DIM*DIM], g_wvt[DIM*DIM];
__device__ __half g_qp16[NTOK], g_kp16[NTOK], g_vt16[NTOK];
__device__ __half g_sch[(size_t)BATCH * SEQ * SEQ];    // 64 MB fp16 scores
__device__ __half g_p16[(size_t)BATCH * SEQ * SEQ];

// ---------------- PTX helpers (sm_80-era: legal on plain sm_103) ----------
__device__ __forceinline__ uint32_t s2u(const void* p) {
    uint32_t a;
    asm("{ .reg .u64 t; cvta.to.shared.u64 t, %1; cvt.u32.u64 %0, t; }"
        : "=r"(a) : "l"(p));
    return a;
}
__device__ __forceinline__ void cpa16(uint32_t s, const void* g) {
    asm volatile("cp.async.cg.shared.global [%0], [%1], 16;" :: "r"(s), "l"(g));
}
__device__ __forceinline__ void cpa_commit() {
    asm volatile("cp.async.commit_group;" ::: "memory");
}
template <int N>
__device__ __forceinline__ void cpa_wait() {
    asm volatile("cp.async.wait_group %0;" :: "n"(N) : "memory");
}
__device__ __forceinline__ void ldsm4(uint32_t* r, uint32_t a) {
    asm volatile("ldmatrix.sync.aligned.m8n8.x4.shared.b16 {%0,%1,%2,%3}, [%4];"
        : "=r"(r[0]), "=r"(r[1]), "=r"(r[2]), "=r"(r[3]) : "r"(a));
}
__device__ __forceinline__ void mma_f16(float* d, const uint32_t* a, const uint32_t* b) {
    asm volatile(
        "mma.sync.aligned.m16n8k16.row.col.f32.f16.f16.f32 "
        "{%0,%1,%2,%3},{%4,%5,%6,%7},{%8,%9},{%0,%1,%2,%3};"
        : "+f"(d[0]), "+f"(d[1]), "+f"(d[2]), "+f"(d[3])
        : "r"(a[0]), "r"(a[1]), "r"(a[2]), "r"(a[3]), "r"(b[0]), "r"(b[1]));
}

// ===========================================================================
// mma.sync fp16 GEMM:  C[M,N] = (A * B^T + bias) * scale   (per grid.z batch)
//   A: [M,K] K-major fp16,  B: [N,K] K-major fp16
//   CTA tile 128x256, KC=64, 3-stage cp.async, 512 threads,
//   16 warps (2m x 8n), 64x32 per warp.
//   BIAS_MODE: 0 none, 1 per-col bias[n], 2 per-row bias[m]
//   OUT_MODE:  0 fp32 Cf, 1 fp16 Ch
// ===========================================================================
#define BM 128
#define BN 256
#define KC 64
#define NSTAGE 3
#define STB 49152u                    // A 16K | B 32K per stage
#define GEMM_SMEM (NSTAGE * STB)      // 144 KB

template <int BIAS_MODE, int OUT_MODE>
__global__ void __launch_bounds__(512, 1)
gemmx(const __half* __restrict__ A, const __half* __restrict__ B,
      const float* __restrict__ bias,
      float* __restrict__ Cf, __half* __restrict__ Ch,
      int K, int lda, int ldb, int ldc,
      long long sA, long long sB, long long sC, float scale)
{
    extern __shared__ __align__(1024) char smem[];
    const uint32_t sb = s2u(smem);

    const int tid = threadIdx.x, wid = tid >> 5, lane = tid & 31;
    const long long z = blockIdx.z;
    const int m0 = blockIdx.y * BM, n0 = blockIdx.x * BN;

    const __half* pA = A + z * sA + (long long)m0 * lda;
    const __half* pB = B + z * sB + (long long)n0 * ldb;

    // ---- stage loader: A 128 rows, B 256 rows x 8 x 16B chunks, XOR swizzle
    auto load_stage = [&](int slot, int k0) {
        const uint32_t st = sb + (uint32_t)slot * STB;
#pragma unroll
        for (int j = 0; j < 2; j++) {             // A: 1024 chunks / 512 thr
            const int i = tid + 512 * j;
            const int r = i >> 3, ch = i & 7;
            const uint32_t o = (uint32_t)r * 128 + (uint32_t)((ch ^ (r & 7)) << 4);
            cpa16(st + o, pA + (long long)r * lda + k0 + ch * 8);
        }
#pragma unroll
        for (int j = 0; j < 4; j++) {             // B: 2048 chunks / 512 thr
            const int i = tid + 512 * j;
            const int r = i >> 3, ch = i & 7;
            const uint32_t o = (uint32_t)r * 128 + (uint32_t)((ch ^ (r & 7)) << 4);
            cpa16(st + 16384 + o, pB + (long long)r * ldb + k0 + ch * 8);
        }
    };

    // ---- warp/thread tiling: 2 warps over M (64 each), 8 over N (32 each)
    const int warp_m = (wid & 1) * 64;
    const int warp_n = (wid >> 1) * 32;

    const int a_row = lane & 15;
    const int a_k   = lane >> 4;
    const int b_row = (lane & 7) | ((lane & 16) >> 1);
    const int b_k   = (lane >> 3) & 1;
    const int swzA  = a_row & 7, swzB = b_row & 7;

    uint32_t rbA[4], rbB[2];
#pragma unroll
    for (int mt = 0; mt < 4; mt++) rbA[mt] = (uint32_t)(warp_m + mt * 16 + a_row) * 128;
#pragma unroll
    for (int p = 0; p < 2; p++)    rbB[p]  = (uint32_t)(warp_n + p * 16 + b_row) * 128;

    float acc[4][4][4];
#pragma unroll
    for (int mt = 0; mt < 4; mt++)
#pragma unroll
        for (int nt = 0; nt < 4; nt++)
#pragma unroll
            for (int e = 0; e < 4; e++) acc[mt][nt][e] = 0.f;

    const int NC = K / KC;

    load_stage(0, 0);      cpa_commit();
    load_stage(1, KC);     cpa_commit();

    for (int c = 0; c < NC; c++) {
        if (c == NC - 1) cpa_wait<0>(); else cpa_wait<1>();
        __syncthreads();

        if (c + 2 < NC) { load_stage((c + 2) % NSTAGE, (c + 2) * KC); cpa_commit(); }

        const uint32_t st = sb + (uint32_t)(c % NSTAGE) * STB;
#pragma unroll
        for (int ks = 0; ks < 4; ks++) {
            const uint32_t chA = (uint32_t)(((2 * ks + a_k) ^ swzA) << 4);
            const uint32_t chB = (uint32_t)(((2 * ks + b_k) ^ swzB) << 4);

            uint32_t af[4][4];
#pragma unroll
            for (int mt = 0; mt < 4; mt++)
                ldsm4(af[mt], st + rbA[mt] + chA);
            uint32_t bf[2][4];
#pragma unroll
            for (int p = 0; p < 2; p++)
                ldsm4(bf[p], st + 16384 + rbB[p] + chB);
#pragma unroll
            for (int mt = 0; mt < 4; mt++)
#pragma unroll
                for (int nt = 0; nt < 4; nt++)
                    mma_f16(acc[mt][nt], af[mt], &bf[nt >> 1][(nt & 1) * 2]);
        }
    }

    // ---- epilogue straight from registers
    const int r0 = m0 + warp_m + (lane >> 2);
    const int c0 = n0 + warp_n + (lane & 3) * 2;
#pragma unroll
    for (int nt = 0; nt < 4; nt++) {
        const int col = c0 + nt * 8;
        float bc0 = 0.f, bc1 = 0.f;
        if (BIAS_MODE == 1) { bc0 = bias[col]; bc1 = bias[col + 1]; }
#pragma unroll
        for (int mt = 0; mt < 4; mt++) {
#pragma unroll
            for (int half = 0; half < 2; half++) {
                const int row = r0 + mt * 16 + half * 8;
                float br = 0.f;
                if (BIAS_MODE == 2) br = bias[row];
                float x0 = acc[mt][nt][2 * half + 0];
                float x1 = acc[mt][nt][2 * half + 1];
                if (BIAS_MODE == 1) { x0 += bc0; x1 += bc1; }
                if (BIAS_MODE == 2) { x0 += br;  x1 += br;  }
                x0 *= scale; x1 *= scale;

                const long long base = z * sC + (long long)row * ldc + col;
                if (OUT_MODE == 0) {
                    *(float2*)(Cf + base) = make_float2(x0, x1);
                } else {
                    __half2 hh; hh.x = __float2half_rn(x0); hh.y = __float2half_rn(x1);
                    *(__half2*)(Ch + base) = hh;
                }
            }
        }
    }
}

// ---------------- fp32 -> fp16 round, batched over q/k/v -------------------
__global__ void __launch_bounds__(256)
round3_kernel(const float* __restrict__ x0, __half* __restrict__ h0,
              const float* __restrict__ x1, __half* __restrict__ h1,
              const float* __restrict__ x2, __half* __restrict__ h2, int n4)
{
    const float* x = (blockIdx.y == 0) ? x0 : (blockIdx.y == 1) ? x1 : x2;
    __half*      h = (blockIdx.y == 0) ? h0 : (blockIdx.y == 1) ? h1 : h2;
    int i = blockIdx.x * 256 + threadIdx.x;
    if (i >= n4) return;
    float4 a = ((const float4*)x)[i];
    __half2 p0; p0.x = __float2half_rn(a.x); p0.y = __float2half_rn(a.y);
    __half2 p1; p1.x = __float2half_rn(a.z); p1.y = __float2half_rn(a.w);
    ((__half2*)h)[2*i] = p0; ((__half2*)h)[2*i+1] = p1;
}

// ---------------- W [K,N] -> W^T [N,K] fp16, batched over 3 weights --------
__global__ void __launch_bounds__(256)
troundW3(const float* __restrict__ W0, __half* __restrict__ T0,
         const float* __restrict__ W1, __half* __restrict__ T1,
         const float* __restrict__ W2, __half* __restrict__ T2)
{
    const float* W = (blockIdx.z == 0) ? W0 : (blockIdx.z == 1) ? W1 : W2;
    __half*      T = (blockIdx.z == 0) ? T0 : (blockIdx.z == 1) ? T1 : T2;

    __shared__ float t[32][33];
    const int bx = blockIdx.x * 32;   // n
    const int by = blockIdx.y * 32;   // k
    const int x = threadIdx.x & 31, y = threadIdx.x >> 5;
#pragma unroll
    for (int j = 0; j < 32; j += 8)
        t[y + j][x] = W[(long long)(by + y + j) * DIM + bx + x];
    __syncthreads();
#pragma unroll
    for (int j = 0; j < 32; j += 8) {
        long long o = (long long)(bx + y + j) * DIM + by + x;
        T[o] = __float2half_rn(t[x][y + j]);
    }
}

// ---------------- softmax rows (fp16 in) -> fp16 P --------------------------
__global__ void __launch_bounds__(256)
softmax_h(const __half* __restrict__ S, __half* __restrict__ P)
{
    const __half* row = S + (size_t)blockIdx.x * SEQ;
    const int t = threadIdx.x;

    float v[8];
    float m = -3.4e38f;
#pragma unroll
    for (int i = 0; i < 8; i++) {
        v[i] = __half2float(row[t + i * 256]);
        m = fmaxf(m, v[i]);
    }

    __shared__ float red[8];
#pragma unroll
    for (int o = 16; o; o >>= 1) m = fmaxf(m, __shfl_xor_sync(0xffffffffu, m, o));
    if ((t & 31) == 0) red[t >> 5] = m;
    __syncthreads();
    m = red[0];
#pragma unroll
    for (int w = 1; w < 8; w++) m = fmaxf(m, red[w]);
    __syncthreads();

    float s = 0.f;
#pragma unroll
    for (int i = 0; i < 8; i++) { v[i] = __expf(v[i] - m); s += v[i]; }
#pragma unroll
    for (int o = 16; o; o >>= 1) s += __shfl_xor_sync(0xffffffffu, s, o);
    if ((t & 31) == 0) red[t >> 5] = s;
    __syncthreads();
    s = 0.f;
#pragma unroll
    for (int w = 0; w < 8; w++) s += red[w];

    const float inv = 1.0f / s;
    const size_t rb = (size_t)blockIdx.x * SEQ;
#pragma unroll
    for (int i = 0; i < 8; i++)
        P[rb + t + i * 256] = __float2half_rn(v[i] * inv);
}

// ===========================================================================
extern "C" void kernel_launch(void* const* d_in, const int* in_sizes, int n_in,
                              void* d_out, int out_size)
{
    const float* q  = (const float*)d_in[0];
    const float* k  = (const float*)d_in[1];
    const float* v  = (const float*)d_in[2];
    const float* Wq = (const float*)d_in[3];
    const float* bq = (const float*)d_in[4];
    const float* Wk = (const float*)d_in[5];
    const float* bk = (const float*)d_in[6];
    const float* Wv = (const float*)d_in[7];
    const float* bv = (const float*)d_in[8];
    float* out = (float*)d_out;

    __half *q16,*k16,*v16, *wqt,*wkt,*wvt, *qp16,*kp16,*vt16, *sch,*p16;
    cudaGetSymbolAddress((void**)&q16, g_q16);
    cudaGetSymbolAddress((void**)&k16, g_k16);
    cudaGetSymbolAddress((void**)&v16, g_v16);
    cudaGetSymbolAddress((void**)&wqt, g_wqt);
    cudaGetSymbolAddress((void**)&wkt, g_wkt);
    cudaGetSymbolAddress((void**)&wvt, g_wvt);
    cudaGetSymbolAddress((void**)&qp16, g_qp16);
    cudaGetSymbolAddress((void**)&kp16, g_kp16);
    cudaGetSymbolAddress((void**)&vt16, g_vt16);
    cudaGetSymbolAddress((void**)&sch, g_sch);
    cudaGetSymbolAddress((void**)&p16, g_p16);

    cudaFuncSetAttribute(gemmx<1, 1>, cudaFuncAttributeMaxDynamicSharedMemorySize, GEMM_SMEM);
    cudaFuncSetAttribute(gemmx<2, 1>, cudaFuncAttributeMaxDynamicSharedMemorySize, GEMM_SMEM);
    cudaFuncSetAttribute(gemmx<0, 1>, cudaFuncAttributeMaxDynamicSharedMemorySize, GEMM_SMEM);
    cudaFuncSetAttribute(gemmx<0, 0>, cudaFuncAttributeMaxDynamicSharedMemorySize, GEMM_SMEM);

    const float qscale = 0.04419417382415922f;   // 1/sqrt(512), applied to scores
    const int n4 = (int)(NTOK / 4);

    // 1) conversions (2 batched launches)
    round3_kernel<<<dim3((n4 + 255) / 256, 3), 256>>>(q, q16, k, k16, v, v16, n4);
    troundW3<<<dim3(16, 16, 3), 256>>>(Wq, wqt, Wk, wkt, Wv, wvt);

    // 2) projections (N=512 -> grid.x = 2)
    gemmx<1, 1><<<dim3(2, 128, 1), 512, GEMM_SMEM>>>(
        q16, wqt, bq, nullptr, qp16, DIM, DIM, DIM, DIM, 0, 0, 0, 1.0f);
    gemmx<1, 1><<<dim3(2, 128, 1), 512, GEMM_SMEM>>>(
        k16, wkt, bk, nullptr, kp16, DIM, DIM, DIM, DIM, 0, 0, 0, 1.0f);
    // vpT[d,t] = WvT . v^T + bv[d]  -> fp16, ldc = 16384 (token-major rows)
    gemmx<2, 1><<<dim3(64, 4, 1), 512, GEMM_SMEM>>>(
        wvt, v16, bv, nullptr, vt16, DIM, DIM, DIM, MTOT, 0, 0, 0, 1.0f);

    // 3) scores: per batch S = (qp . kp^T) * qscale -> fp16
    gemmx<0, 1><<<dim3(8, 16, BATCH), 512, GEMM_SMEM>>>(
        qp16, kp16, nullptr, nullptr, sch,
        DIM, DIM, DIM, SEQ,
        (long long)SEQ * DIM, (long long)SEQ * DIM, (long long)SEQ * SEQ, qscale);

    // 4) softmax -> fp16 P
    softmax_h<<<BATCH * SEQ, 256>>>(sch, p16);

    // 5) O = P vp : B[n=d, k=s] = vpT[d, z*2048 + s]
    gemmx<0, 0><<<dim3(2, 16, BATCH), 512, GEMM_SMEM>>>(
        p16, vt16, nullptr, out, nullptr,
        SEQ, SEQ, MTOT, DIM,
        (long long)SEQ * SEQ, (long long)SEQ, (long long)SEQ * DIM, 1.0f);
}